// round 9
// baseline (speedup 1.0000x reference)
#include <cuda_runtime.h>
#include <cuda_bf16.h>
#include <cstdint>

#define SEQ 386
#define NP  385
#define HH  256
#define EMB 128
#define G4  1024
#define OSTR (385*129)

typedef unsigned long long ull;

__device__ float g_emb[SEQ][EMB];
__device__ float g_xpre[2][SEQ][G4];
__device__ float g_h[2][SEQ][HH];
__device__ float g_U[NP][HH];
__device__ float g_V[NP][HH];
__device__ ull   g_w2p[256 * 64];   // [k][cpair] packed label w2

__device__ __forceinline__ ull pack2(float lo, float hi) {
    ull r; asm("mov.b64 %0, {%1, %2};" : "=l"(r) : "f"(lo), "f"(hi)); return r;
}
__device__ __forceinline__ void unpack2(ull v, float& lo, float& hi) {
    asm("mov.b64 {%0, %1}, %2;" : "=f"(lo), "=f"(hi) : "l"(v));
}
__device__ __forceinline__ void ffma2(ull& d, ull a, ull b) {
    asm("fma.rn.f32x2 %0, %1, %2, %0;" : "+l"(d) : "l"(a), "l"(b));
}
__device__ __forceinline__ unsigned smem_u32(const void* p) {
    unsigned a;
    asm("{ .reg .u64 t; cvta.to.shared.u64 t, %1; cvt.u32.u64 %0, t; }" : "=r"(a) : "l"(p));
    return a;
}
__device__ __forceinline__ void st_cluster(unsigned addr, int rank, float v) {
    unsigned ra;
    asm volatile("mapa.shared::cluster.u32 %0, %1, %2;" : "=r"(ra) : "r"(addr), "r"(rank));
    asm volatile("st.shared::cluster.f32 [%0], %1;" :: "r"(ra), "f"(v) : "memory");
}
__device__ __forceinline__ void mbar_arrive_remote(unsigned local_addr, int rank) {
    unsigned ra;
    asm volatile("mapa.shared::cluster.u32 %0, %1, %2;" : "=r"(ra) : "r"(local_addr), "r"(rank));
    asm volatile("mbarrier.arrive.release.cluster.shared::cluster.b64 _, [%0];" :: "r"(ra) : "memory");
}
__device__ __forceinline__ void mbar_init(unsigned addr, unsigned cnt) {
    asm volatile("mbarrier.init.shared.b64 [%0], %1;" :: "r"(addr), "r"(cnt) : "memory");
}
__device__ __forceinline__ void mbar_wait(unsigned addr, unsigned parity) {
    asm volatile(
        "{\n\t.reg .pred P;\n\t"
        "LW_%=:\n\t"
        "mbarrier.try_wait.parity.acquire.cluster.shared::cta.b64 P, [%0], %1, 0x989680;\n\t"
        "@P bra.uni LD_%=;\n\t"
        "bra.uni LW_%=;\n\t"
        "LD_%=:\n\t}"
        :: "r"(addr), "r"(parity) : "memory");
}
__device__ __forceinline__ void cluster_sync_() {
    asm volatile("barrier.cluster.arrive.aligned;" ::: "memory");
    asm volatile("barrier.cluster.wait.aligned;" ::: "memory");
}
__device__ __forceinline__ float sigx(float x)  { return __fdividef(1.f, 1.f + __expf(-x)); }
__device__ __forceinline__ float tanhx(float x) { return 2.f * __fdividef(1.f, 1.f + __expf(-2.f * x)) - 1.f; }

// ---------- K1: embeddings ----------
__global__ void k_embed(const int* __restrict__ tg, const int* __restrict__ wd,
                        const float* __restrict__ te, const float* __restrict__ we) {
    int t = blockIdx.x, d = threadIdx.x;
    g_emb[t][d] = te[tg[t] * EMB + d] + we[wd[t] * EMB + d];
}

// ---------- K1b: pack label w2 ----------
__global__ void k_w2pack(const float* __restrict__ lab_w2) {
    int idx = blockIdx.x * 256 + threadIdx.x;
    int cp = idx >> 8, k = idx & 255;
    g_w2p[k * 64 + cp] = pack2(lab_w2[(2 * cp) * 256 + k], lab_w2[(2 * cp + 1) * 256 + k]);
}

// ---------- K2: x preactivations ----------
__global__ void __launch_bounds__(1024, 1)
k_xpre(const float* __restrict__ wxf, const float* __restrict__ bfp,
       const float* __restrict__ wxb, const float* __restrict__ bbp) {
    __shared__ float se[8][128];
    __shared__ float wt[1024][9];
    int tid = threadIdx.x, t0 = blockIdx.x * 8, dir = blockIdx.y;
    {
        int tp = tid >> 7, d = tid & 127, t = t0 + tp;
        se[tp][d] = (t < SEQ) ? g_emb[t][d] : 0.f;
    }
    const float* Wx = dir ? wxb : wxf;
    const float* bp = dir ? bbp : bfp;
    float acc[8] = {0, 0, 0, 0, 0, 0, 0, 0};
    for (int d0 = 0; d0 < 128; d0 += 8) {
        __syncthreads();
#pragma unroll
        for (int it = 0; it < 8; ++it) {
            int idx = tid + it * 1024;
            int row = idx >> 3, dd = idx & 7;
            wt[row][dd] = Wx[row * 128 + d0 + dd];
        }
        __syncthreads();
#pragma unroll
        for (int dd = 0; dd < 8; ++dd) {
            float w = wt[tid][dd];
#pragma unroll
            for (int tp = 0; tp < 8; ++tp) acc[tp] += w * se[tp][d0 + dd];
        }
    }
    float bias = bp[tid];
#pragma unroll
    for (int tp = 0; tp < 8; ++tp) {
        int t = t0 + tp;
        if (t < SEQ) g_xpre[dir][t][tid] = acc[tp] + bias;
    }
}

// ---------- K3: BiLSTM, mbarrier-pipelined 8-CTA cluster per direction ----------
__global__ void __cluster_dims__(8, 1, 1) __launch_bounds__(512, 1)
k_lstm(const float* __restrict__ whf, const float* __restrict__ whb) {
    __shared__ __align__(16) float hbuf[2][HH];
    __shared__ __align__(8) ull wr_mbar[2];
    __shared__ __align__(8) ull rd_mbar[2];
    int tid = threadIdx.x;
    int dir = blockIdx.x >> 3, rank = blockIdx.x & 7;
    int ql = tid >> 4, gt = (tid >> 2) & 3, p = tid & 3, lane = tid & 31;
    int row = gt * 256 + rank * 32 + ql;
    const float* Wh = dir ? whb : whf;

    // weight pairs for 16 x LDS.128: base = (p<<6) | ((4m+8p)&63), floats [base, base+4)
    ull wA[16], wB[16];
#pragma unroll
    for (int m = 0; m < 16; ++m) {
        int base = (p << 6) | ((4 * m + 8 * p) & 63);
        const float* wp = Wh + row * 256 + base;
        wA[m] = pack2(wp[0], wp[1]);
        wB[m] = pack2(wp[2], wp[3]);
    }
    ((float*)hbuf)[tid] = 0.f;   // zero both 256-float buffers
    if (tid == 0) {
        mbar_init(smem_u32(&wr_mbar[0]), 256);
        mbar_init(smem_u32(&wr_mbar[1]), 256);
        mbar_init(smem_u32(&rd_mbar[0]), 8);
        mbar_init(smem_u32(&rd_mbar[1]), 8);
    }
    __syncthreads();
    cluster_sync_();

    unsigned wrA0 = smem_u32(&wr_mbar[0]), wrA1 = smem_u32(&wr_mbar[1]);
    unsigned rdA0 = smem_u32(&rd_mbar[0]), rdA1 = smem_u32(&rd_mbar[1]);
    unsigned wph0 = 0, wph1 = 0, rph0 = 0, rph1 = 0;
    bool writer = ((lane & 15) == 0);

    float c_state = 0.f;
    int t = dir ? (SEQ - 1) : 0;
    float xcur = g_xpre[dir][t][row];

    for (int s = 0; s < SEQ; ++s) {
        int cur = s & 1, nxt = cur ^ 1;
        int tn = dir ? (SEQ - 2 - s) : (s + 1);
        float xnext = (s < SEQ - 1) ? g_xpre[dir][tn][row] : 0.f;

        if (s) {   // data-ready wait for hbuf[cur]
            if (cur) { mbar_wait(wrA1, wph1); wph1 ^= 1; }
            else     { mbar_wait(wrA0, wph0); wph0 ^= 1; }
        }

        ull acc = 0ULL;
#pragma unroll
        for (int m = 0; m < 16; ++m) {
            int base = (p << 6) | ((4 * m + 8 * p) & 63);
            ulonglong2 hh = *(const ulonglong2*)&hbuf[cur][base];
            ffma2(acc, wA[m], hh.x);
            ffma2(acc, wB[m], hh.y);
        }
        float a, b; unpack2(acc, a, b);
        float r = a + b;
        r += __shfl_xor_sync(0xffffffffu, r, 1);
        r += __shfl_xor_sync(0xffffffffu, r, 2);
        float pre = r + xcur;

        int base = lane & 16;
        float pi = __shfl_sync(0xffffffffu, pre, base);
        float pf = __shfl_sync(0xffffffffu, pre, base + 4);
        float pg = __shfl_sync(0xffffffffu, pre, base + 8);
        float po = __shfl_sync(0xffffffffu, pre, base + 12);

        float hv = 0.f;
        if (writer) {
            c_state = sigx(pf) * c_state + sigx(pi) * tanhx(pg);
            hv = sigx(po) * tanhx(c_state);
            g_h[dir][t][rank * 32 + ql] = hv;
        }

        __syncthreads();                       // all reads of hbuf[cur] done (CTA)
        if (tid == 0) {                        // broadcast reader-done for buffer cur
            unsigned rdl = cur ? rdA1 : rdA0;
#pragma unroll
            for (int rr = 0; rr < 8; ++rr) mbar_arrive_remote(rdl, rr);
        }

        if (s >= 1 && s < SEQ - 1) {           // backpressure: buffer nxt free?
            if (nxt) { mbar_wait(rdA1, rph1); rph1 ^= 1; }
            else     { mbar_wait(rdA0, rph0); rph0 ^= 1; }
        }

        if (writer && s < SEQ - 1) {
            unsigned la = smem_u32(&hbuf[nxt][rank * 32 + ql]);
            unsigned wrl = nxt ? wrA1 : wrA0;
#pragma unroll
            for (int rr = 0; rr < 8; ++rr) st_cluster(la, rr, hv);
#pragma unroll
            for (int rr = 0; rr < 8; ++rr) mbar_arrive_remote(wrl, rr);
        }
        t = tn;
        xcur = xnext;
    }
    cluster_sync_();
}

// ---------- K4: U/V span transforms ----------
__global__ void __launch_bounds__(256, 1)
k_uv(const float* __restrict__ lab_w1, const float* __restrict__ spl_w1) {
    __shared__ float sh2[512][2];
    int tid = threadIdx.x, k0 = blockIdx.x * 2, which = blockIdx.y;
    for (int idx = tid; idx < 1024; idx += 256) {
        int d = idx >> 1, kk = idx & 1, k = k0 + kk;
        float v = 0.f;
        if (k < NP) v = (d < 256) ? g_h[0][k][d] : -g_h[1][k + 1][d - 256];
        sh2[d][kk] = v;
    }
    __syncthreads();
    const float* w1 = which ? spl_w1 : lab_w1;
    int w = tid >> 5, lane = tid & 31;
    float (*dst)[HH] = which ? g_V : g_U;
#pragma unroll 2
    for (int cx = 0; cx < 32; ++cx) {
        int c = w * 32 + cx;
        const float* wr = w1 + c * 512;
        ull acc = 0ULL;
#pragma unroll
        for (int m = 0; m < 16; ++m) {
            int d = m * 32 + lane;
            float wv = wr[d];
            ffma2(acc, pack2(wv, wv), *(const ull*)&sh2[d][0]);
        }
        float a, b; unpack2(acc, a, b);
#pragma unroll
        for (int off = 16; off; off >>= 1) {
            a += __shfl_xor_sync(0xffffffffu, a, off);
            b += __shfl_xor_sync(0xffffffffu, b, off);
        }
        if (lane == 0) {
            if (k0     < NP) dst[k0    ][c] = a;
            if (k0 + 1 < NP) dst[k0 + 1][c] = b;
        }
    }
}

// ---------- K5: pairwise outputs ----------
#define HIDSTR 260
#define SM_HID   131072
#define SM_LB1   (SM_HID + 64 * HIDSTR * 4)
#define SM_SB1   (SM_LB1 + 1024)
#define SM_SW2   (SM_SB1 + 1024)
#define SM_LB2   (SM_SW2 + 1024)
#define SM_TOTAL (SM_LB2 + 512)

__global__ void __launch_bounds__(256, 1)
k_out(const float* __restrict__ lab_b1, const float* __restrict__ lab_b2,
      const float* __restrict__ spl_b1, const float* __restrict__ spl_w2,
      const float* __restrict__ spl_b2, float* __restrict__ out) {
    extern __shared__ char sm[];
    ull*   W2P  = (ull*)sm;
    float* HID2 = (float*)(sm + SM_HID);
    float* LB1  = (float*)(sm + SM_LB1);
    float* SB1  = (float*)(sm + SM_SB1);
    float* SW2  = (float*)(sm + SM_SW2);
    float* LB2  = (float*)(sm + SM_LB2);
    int tid = threadIdx.x;
    int j0 = blockIdx.x * 16, i0 = blockIdx.y * 4;

    {
        const float4* src = (const float4*)g_w2p;
        float4* dst = (float4*)W2P;
        for (int it = tid; it < 8192; it += 256) dst[it] = src[it];
    }
    LB1[tid] = lab_b1[tid];
    SB1[tid] = spl_b1[tid];
    SW2[tid] = spl_w2[tid];
    if (tid < 128) LB2[tid] = lab_b2[tid];
    __syncthreads();

    int wp = tid >> 5, lane = tid & 31;
    float sb2 = spl_b2[0];
    for (int px = 0; px < 8; ++px) {
        int p = wp * 8 + px;
        int i = i0 + (p >> 4), j = j0 + (p & 15);
        int ic = min(i, NP - 1), jc = min(j, NP - 1);
        const float* Uj = g_U[jc]; const float* Ui = g_U[ic];
        const float* Vj = g_V[jc]; const float* Vi = g_V[ic];
        float sacc = 0.f;
#pragma unroll
        for (int m = 0; m < 8; ++m) {
            int k = m * 32 + lane;
            HID2[p * HIDSTR + k] = fmaxf(Uj[k] - Ui[k] + LB1[k], 0.f);
            sacc += fmaxf(Vj[k] - Vi[k] + SB1[k], 0.f) * SW2[k];
        }
#pragma unroll
        for (int off = 16; off; off >>= 1)
            sacc += __shfl_xor_sync(0xffffffffu, sacc, off);
        if (lane == 0 && i < NP && j < NP)
            out[i * OSTR + j * 129 + 128] = sacc + sb2;
    }
    __syncthreads();

    int pg = tid >> 4, cg = tid & 15;
    ull acc[4][4];
#pragma unroll
    for (int a = 0; a < 4; ++a)
#pragma unroll
        for (int b = 0; b < 4; ++b) acc[a][b] = 0ULL;

    const float* hb = HID2 + pg * 4 * HIDSTR;
    const ull*  wb = W2P + cg;
#pragma unroll 2
    for (int k = 0; k < 256; ++k) {
        float h0 = hb[k], h1 = hb[HIDSTR + k], h2 = hb[2 * HIDSTR + k], h3 = hb[3 * HIDSTR + k];
        ull H0 = pack2(h0, h0), H1 = pack2(h1, h1), H2 = pack2(h2, h2), H3 = pack2(h3, h3);
        ull w0 = wb[k * 64], w1 = wb[k * 64 + 16], w2 = wb[k * 64 + 32], w3 = wb[k * 64 + 48];
        ffma2(acc[0][0], H0, w0); ffma2(acc[0][1], H0, w1); ffma2(acc[0][2], H0, w2); ffma2(acc[0][3], H0, w3);
        ffma2(acc[1][0], H1, w0); ffma2(acc[1][1], H1, w1); ffma2(acc[1][2], H1, w2); ffma2(acc[1][3], H1, w3);
        ffma2(acc[2][0], H2, w0); ffma2(acc[2][1], H2, w1); ffma2(acc[2][2], H2, w2); ffma2(acc[2][3], H2, w3);
        ffma2(acc[3][0], H3, w0); ffma2(acc[3][1], H3, w1); ffma2(acc[3][2], H3, w2); ffma2(acc[3][3], H3, w3);
    }
#pragma unroll
    for (int pp = 0; pp < 4; ++pp) {
        int p = pg * 4 + pp;
        int i = i0 + (p >> 4), j = j0 + (p & 15);
        if (i >= NP || j >= NP) continue;
        float* o = out + i * OSTR + j * 129;
#pragma unroll
        for (int q = 0; q < 4; ++q) {
            int cp = cg + 16 * q;
            float lo, hi; unpack2(acc[pp][q], lo, hi);
            o[2 * cp]     = lo + LB2[2 * cp];
            o[2 * cp + 1] = hi + LB2[2 * cp + 1];
        }
    }
}

extern "C" void kernel_launch(void* const* d_in, const int* in_sizes, int n_in,
                              void* d_out, int out_size) {
    const int*   tag_ids  = (const int*)d_in[0];
    const int*   word_ids = (const int*)d_in[1];
    const float* tag_emb  = (const float*)d_in[2];
    const float* word_emb = (const float*)d_in[3];
    const float* wxf = (const float*)d_in[4];
    const float* whf = (const float*)d_in[5];
    const float* bf  = (const float*)d_in[6];
    const float* wxb = (const float*)d_in[7];
    const float* whb = (const float*)d_in[8];
    const float* bb  = (const float*)d_in[9];
    const float* lab_w1 = (const float*)d_in[10];
    const float* lab_b1 = (const float*)d_in[11];
    const float* lab_w2 = (const float*)d_in[12];
    const float* lab_b2 = (const float*)d_in[13];
    const float* spl_w1 = (const float*)d_in[14];
    const float* spl_b1 = (const float*)d_in[15];
    const float* spl_w2 = (const float*)d_in[16];
    const float* spl_b2 = (const float*)d_in[17];
    float* out = (float*)d_out;

    static int smem_set = 0;
    if (!smem_set) {
        cudaFuncSetAttribute(k_out, cudaFuncAttributeMaxDynamicSharedMemorySize, SM_TOTAL);
        smem_set = 1;
    }

    k_embed<<<SEQ, EMB>>>(tag_ids, word_ids, tag_emb, word_emb);
    k_w2pack<<<64, 256>>>(lab_w2);
    k_xpre<<<dim3(49, 2), 1024>>>(wxf, bf, wxb, bb);
    k_lstm<<<16, 512>>>(whf, whb);
    k_uv<<<dim3(193, 2), 256>>>(lab_w1, spl_w1);
    k_out<<<dim3(25, 97), 256, SM_TOTAL>>>(lab_b1, lab_b2, spl_b1, spl_w2, spl_b2, out);
}

// round 10
// speedup vs baseline: 1.4128x; 1.4128x over previous
#include <cuda_runtime.h>
#include <cuda_bf16.h>
#include <cstdint>

#define SEQ 386
#define NP  385
#define HH  256
#define EMB 128
#define G4  1024
#define OSTR (385*129)

typedef unsigned long long ull;

__device__ float g_emb[SEQ][EMB];
__device__ float g_xpre[2][SEQ][G4];
__device__ float g_h[2][SEQ][HH];
__device__ float g_U[NP][HH];
__device__ float g_V[NP][HH];
__device__ ull   g_w2p[256 * 64];   // [k][cpair] packed label w2

__device__ __forceinline__ ull pack2(float lo, float hi) {
    ull r; asm("mov.b64 %0, {%1, %2};" : "=l"(r) : "f"(lo), "f"(hi)); return r;
}
__device__ __forceinline__ void unpack2(ull v, float& lo, float& hi) {
    asm("mov.b64 {%0, %1}, %2;" : "=f"(lo), "=f"(hi) : "l"(v));
}
__device__ __forceinline__ void ffma2(ull& d, ull a, ull b) {
    asm("fma.rn.f32x2 %0, %1, %2, %0;" : "+l"(d) : "l"(a), "l"(b));
}
__device__ __forceinline__ unsigned smem_u32(const void* p) {
    unsigned a;
    asm("{ .reg .u64 t; cvta.to.shared.u64 t, %1; cvt.u32.u64 %0, t; }" : "=r"(a) : "l"(p));
    return a;
}
__device__ __forceinline__ unsigned mapa_rank(unsigned addr, int rank) {
    unsigned ra;
    asm volatile("mapa.shared::cluster.u32 %0, %1, %2;" : "=r"(ra) : "r"(addr), "r"(rank));
    return ra;
}
__device__ __forceinline__ void mbar_init(unsigned addr, unsigned cnt) {
    asm volatile("mbarrier.init.shared.b64 [%0], %1;" :: "r"(addr), "r"(cnt) : "memory");
}
__device__ __forceinline__ void mbar_wait(unsigned addr, unsigned parity) {
    asm volatile(
        "{\n\t.reg .pred P;\n\t"
        "LW_%=:\n\t"
        "mbarrier.try_wait.parity.acquire.cluster.shared::cta.b64 P, [%0], %1, 0x989680;\n\t"
        "@P bra.uni LD_%=;\n\t"
        "bra.uni LW_%=;\n\t"
        "LD_%=:\n\t}"
        :: "r"(addr), "r"(parity) : "memory");
}
__device__ __forceinline__ void cluster_sync_() {
    asm volatile("barrier.cluster.arrive.aligned;" ::: "memory");
    asm volatile("barrier.cluster.wait.aligned;" ::: "memory");
}
__device__ __forceinline__ float sigx(float x)  { return __fdividef(1.f, 1.f + __expf(-x)); }
__device__ __forceinline__ float tanhx(float x) { return 2.f * __fdividef(1.f, 1.f + __expf(-2.f * x)) - 1.f; }

// ---------- K1: embeddings ----------
__global__ void k_embed(const int* __restrict__ tg, const int* __restrict__ wd,
                        const float* __restrict__ te, const float* __restrict__ we) {
    int t = blockIdx.x, d = threadIdx.x;
    g_emb[t][d] = te[tg[t] * EMB + d] + we[wd[t] * EMB + d];
}

// ---------- K1b: pack label w2 ----------
__global__ void k_w2pack(const float* __restrict__ lab_w2) {
    int idx = blockIdx.x * 256 + threadIdx.x;
    int cp = idx >> 8, k = idx & 255;
    g_w2p[k * 64 + cp] = pack2(lab_w2[(2 * cp) * 256 + k], lab_w2[(2 * cp + 1) * 256 + k]);
}

// ---------- K2: x preactivations ----------
__global__ void __launch_bounds__(1024, 1)
k_xpre(const float* __restrict__ wxf, const float* __restrict__ bfp,
       const float* __restrict__ wxb, const float* __restrict__ bbp) {
    __shared__ float se[8][128];
    __shared__ float wt[1024][9];
    int tid = threadIdx.x, t0 = blockIdx.x * 8, dir = blockIdx.y;
    {
        int tp = tid >> 7, d = tid & 127, t = t0 + tp;
        se[tp][d] = (t < SEQ) ? g_emb[t][d] : 0.f;
    }
    const float* Wx = dir ? wxb : wxf;
    const float* bp = dir ? bbp : bfp;
    float acc[8] = {0, 0, 0, 0, 0, 0, 0, 0};
    for (int d0 = 0; d0 < 128; d0 += 8) {
        __syncthreads();
#pragma unroll
        for (int it = 0; it < 8; ++it) {
            int idx = tid + it * 1024;
            int row = idx >> 3, dd = idx & 7;
            wt[row][dd] = Wx[row * 128 + d0 + dd];
        }
        __syncthreads();
#pragma unroll
        for (int dd = 0; dd < 8; ++dd) {
            float w = wt[tid][dd];
#pragma unroll
            for (int tp = 0; tp < 8; ++tp) acc[tp] += w * se[tp][d0 + dd];
        }
    }
    float bias = bp[tid];
#pragma unroll
    for (int tp = 0; tp < 8; ++tp) {
        int t = t0 + tp;
        if (t < SEQ) g_xpre[dir][t][tid] = acc[tp] + bias;
    }
}

// ---------- K3: BiLSTM, aggregated-mbarrier 8-CTA cluster per direction ----------
__global__ void __cluster_dims__(8, 1, 1) __launch_bounds__(512, 1)
k_lstm(const float* __restrict__ whf, const float* __restrict__ whb) {
    __shared__ __align__(16) float hbuf[2][HH];
    __shared__ __align__(16) float stag[32];
    __shared__ __align__(8) ull wr_mbar[2];
    int tid = threadIdx.x;
    int dir = blockIdx.x >> 3, rank = blockIdx.x & 7;
    int ql = tid >> 4, p = tid & 3, gt = (tid >> 2) & 3, lane = tid & 31;
    int row = gt * 256 + rank * 32 + ql;
    const float* Wh = dir ? whb : whf;

    ull wA[16], wB[16];
#pragma unroll
    for (int m = 0; m < 16; ++m) {
        int base = (p << 6) | ((4 * m + 8 * p) & 63);
        const float* wp = Wh + row * 256 + base;
        wA[m] = pack2(wp[0], wp[1]);
        wB[m] = pack2(wp[2], wp[3]);
    }
    ((float*)hbuf)[tid] = 0.f;   // zero both 256-float buffers
    if (tid == 0) {
        mbar_init(smem_u32(&wr_mbar[0]), 8);
        mbar_init(smem_u32(&wr_mbar[1]), 8);
    }
    __syncthreads();
    cluster_sync_();

    unsigned wrA0 = smem_u32(&wr_mbar[0]), wrA1 = smem_u32(&wr_mbar[1]);
    unsigned ph0 = 0, ph1 = 0;
    bool writer = ((lane & 15) == 0);

    float c_state = 0.f;
    int t = dir ? (SEQ - 1) : 0;
    float xcur = g_xpre[dir][t][row];

    for (int s = 0; s < SEQ; ++s) {
        int cur = s & 1, nxt = cur ^ 1;
        int tn = dir ? (SEQ - 2 - s) : (s + 1);
        float xnext = (s < SEQ - 1) ? g_xpre[dir][tn][row] : 0.f;

        if (s) {   // data-ready for hbuf[cur] (8 aggregated arrivals)
            if (cur) { mbar_wait(wrA1, ph1); ph1 ^= 1; }
            else     { mbar_wait(wrA0, ph0); ph0 ^= 1; }
        }

        ull acc = 0ULL;
#pragma unroll
        for (int m = 0; m < 16; ++m) {
            int base = (p << 6) | ((4 * m + 8 * p) & 63);
            ulonglong2 hh = *(const ulonglong2*)&hbuf[cur][base];
            ffma2(acc, wA[m], hh.x);
            ffma2(acc, wB[m], hh.y);
        }
        float a, b; unpack2(acc, a, b);
        float r = a + b;
        r += __shfl_xor_sync(0xffffffffu, r, 1);
        r += __shfl_xor_sync(0xffffffffu, r, 2);
        float pre = r + xcur;

        int base = lane & 16;
        float pi = __shfl_sync(0xffffffffu, pre, base);
        float pf = __shfl_sync(0xffffffffu, pre, base + 4);
        float pg = __shfl_sync(0xffffffffu, pre, base + 8);
        float po = __shfl_sync(0xffffffffu, pre, base + 12);

        if (writer) {
            c_state = sigx(pf) * c_state + sigx(pi) * tanhx(pg);
            float hv = sigx(po) * tanhx(c_state);
            g_h[dir][t][rank * 32 + ql] = hv;
            stag[ql] = hv;
        }
        __syncthreads();   // staging complete; also: all reads of hbuf[cur] done

        if (s < SEQ - 1 && tid < 8) {
            // lane r pushes this CTA's 32 h values into CTA r's hbuf[nxt] slice,
            // then one release-arrive on CTA r's wr_mbar[nxt].
            const ull* sp = (const ull*)stag;
            unsigned dst = mapa_rank(smem_u32(&hbuf[nxt][rank * 32]), tid);
#pragma unroll
            for (int m = 0; m < 16; ++m)
                asm volatile("st.shared::cluster.b64 [%0], %1;"
                             :: "r"(dst + m * 8), "l"(sp[m]) : "memory");
            unsigned rb = mapa_rank(nxt ? wrA1 : wrA0, tid);
            asm volatile("mbarrier.arrive.release.cluster.shared::cluster.b64 _, [%0];"
                         :: "r"(rb) : "memory");
        }
        t = tn;
        xcur = xnext;
    }
    cluster_sync_();
}

// ---------- K4: U/V span transforms ----------
__global__ void __launch_bounds__(256, 1)
k_uv(const float* __restrict__ lab_w1, const float* __restrict__ spl_w1) {
    __shared__ float sh2[512][2];
    int tid = threadIdx.x, k0 = blockIdx.x * 2, which = blockIdx.y;
    for (int idx = tid; idx < 1024; idx += 256) {
        int d = idx >> 1, kk = idx & 1, k = k0 + kk;
        float v = 0.f;
        if (k < NP) v = (d < 256) ? g_h[0][k][d] : -g_h[1][k + 1][d - 256];
        sh2[d][kk] = v;
    }
    __syncthreads();
    const float* w1 = which ? spl_w1 : lab_w1;
    int w = tid >> 5, lane = tid & 31;
    float (*dst)[HH] = which ? g_V : g_U;
#pragma unroll 2
    for (int cx = 0; cx < 32; ++cx) {
        int c = w * 32 + cx;
        const float* wr = w1 + c * 512;
        ull acc = 0ULL;
#pragma unroll
        for (int m = 0; m < 16; ++m) {
            int d = m * 32 + lane;
            float wv = wr[d];
            ffma2(acc, pack2(wv, wv), *(const ull*)&sh2[d][0]);
        }
        float a, b; unpack2(acc, a, b);
#pragma unroll
        for (int off = 16; off; off >>= 1) {
            a += __shfl_xor_sync(0xffffffffu, a, off);
            b += __shfl_xor_sync(0xffffffffu, b, off);
        }
        if (lane == 0) {
            if (k0     < NP) dst[k0    ][c] = a;
            if (k0 + 1 < NP) dst[k0 + 1][c] = b;
        }
    }
}

// ---------- K5: pairwise outputs ----------
#define HIDSTR 260
#define SM_HID   131072
#define SM_LB1   (SM_HID + 64 * HIDSTR * 4)
#define SM_SB1   (SM_LB1 + 1024)
#define SM_SW2   (SM_SB1 + 1024)
#define SM_LB2   (SM_SW2 + 1024)
#define SM_TOTAL (SM_LB2 + 512)

__global__ void __launch_bounds__(256, 1)
k_out(const float* __restrict__ lab_b1, const float* __restrict__ lab_b2,
      const float* __restrict__ spl_b1, const float* __restrict__ spl_w2,
      const float* __restrict__ spl_b2, float* __restrict__ out) {
    extern __shared__ char sm[];
    ull*   W2P  = (ull*)sm;
    float* HID2 = (float*)(sm + SM_HID);
    float* LB1  = (float*)(sm + SM_LB1);
    float* SB1  = (float*)(sm + SM_SB1);
    float* SW2  = (float*)(sm + SM_SW2);
    float* LB2  = (float*)(sm + SM_LB2);
    int tid = threadIdx.x;
    int j0 = blockIdx.x * 16, i0 = blockIdx.y * 4;

    {
        const float4* src = (const float4*)g_w2p;
        float4* dst = (float4*)W2P;
        for (int it = tid; it < 8192; it += 256) dst[it] = src[it];
    }
    LB1[tid] = lab_b1[tid];
    SB1[tid] = spl_b1[tid];
    SW2[tid] = spl_w2[tid];
    if (tid < 128) LB2[tid] = lab_b2[tid];
    __syncthreads();

    int wp = tid >> 5, lane = tid & 31;
    float sb2 = spl_b2[0];
    for (int px = 0; px < 8; ++px) {
        int p = wp * 8 + px;
        int i = i0 + (p >> 4), j = j0 + (p & 15);
        int ic = min(i, NP - 1), jc = min(j, NP - 1);
        const float* Uj = g_U[jc]; const float* Ui = g_U[ic];
        const float* Vj = g_V[jc]; const float* Vi = g_V[ic];
        float sacc = 0.f;
#pragma unroll
        for (int m = 0; m < 8; ++m) {
            int k = m * 32 + lane;
            HID2[p * HIDSTR + k] = fmaxf(Uj[k] - Ui[k] + LB1[k], 0.f);
            sacc += fmaxf(Vj[k] - Vi[k] + SB1[k], 0.f) * SW2[k];
        }
#pragma unroll
        for (int off = 16; off; off >>= 1)
            sacc += __shfl_xor_sync(0xffffffffu, sacc, off);
        if (lane == 0 && i < NP && j < NP)
            out[i * OSTR + j * 129 + 128] = sacc + sb2;
    }
    __syncthreads();

    int pg = tid >> 4, cg = tid & 15;
    ull acc[4][4];
#pragma unroll
    for (int a = 0; a < 4; ++a)
#pragma unroll
        for (int b = 0; b < 4; ++b) acc[a][b] = 0ULL;

    const float* hb = HID2 + pg * 4 * HIDSTR;
    const ull*  wb = W2P + cg;
#pragma unroll 2
    for (int k = 0; k < 256; ++k) {
        float h0 = hb[k], h1 = hb[HIDSTR + k], h2 = hb[2 * HIDSTR + k], h3 = hb[3 * HIDSTR + k];
        ull H0 = pack2(h0, h0), H1 = pack2(h1, h1), H2 = pack2(h2, h2), H3 = pack2(h3, h3);
        ull w0 = wb[k * 64], w1 = wb[k * 64 + 16], w2 = wb[k * 64 + 32], w3 = wb[k * 64 + 48];
        ffma2(acc[0][0], H0, w0); ffma2(acc[0][1], H0, w1); ffma2(acc[0][2], H0, w2); ffma2(acc[0][3], H0, w3);
        ffma2(acc[1][0], H1, w0); ffma2(acc[1][1], H1, w1); ffma2(acc[1][2], H1, w2); ffma2(acc[1][3], H1, w3);
        ffma2(acc[2][0], H2, w0); ffma2(acc[2][1], H2, w1); ffma2(acc[2][2], H2, w2); ffma2(acc[2][3], H2, w3);
        ffma2(acc[3][0], H3, w0); ffma2(acc[3][1], H3, w1); ffma2(acc[3][2], H3, w2); ffma2(acc[3][3], H3, w3);
    }
#pragma unroll
    for (int pp = 0; pp < 4; ++pp) {
        int p = pg * 4 + pp;
        int i = i0 + (p >> 4), j = j0 + (p & 15);
        if (i >= NP || j >= NP) continue;
        float* o = out + i * OSTR + j * 129;
#pragma unroll
        for (int q = 0; q < 4; ++q) {
            int cp = cg + 16 * q;
            float lo, hi; unpack2(acc[pp][q], lo, hi);
            o[2 * cp]     = lo + LB2[2 * cp];
            o[2 * cp + 1] = hi + LB2[2 * cp + 1];
        }
    }
}

extern "C" void kernel_launch(void* const* d_in, const int* in_sizes, int n_in,
                              void* d_out, int out_size) {
    const int*   tag_ids  = (const int*)d_in[0];
    const int*   word_ids = (const int*)d_in[1];
    const float* tag_emb  = (const float*)d_in[2];
    const float* word_emb = (const float*)d_in[3];
    const float* wxf = (const float*)d_in[4];
    const float* whf = (const float*)d_in[5];
    const float* bf  = (const float*)d_in[6];
    const float* wxb = (const float*)d_in[7];
    const float* whb = (const float*)d_in[8];
    const float* bb  = (const float*)d_in[9];
    const float* lab_w1 = (const float*)d_in[10];
    const float* lab_b1 = (const float*)d_in[11];
    const float* lab_w2 = (const float*)d_in[12];
    const float* lab_b2 = (const float*)d_in[13];
    const float* spl_w1 = (const float*)d_in[14];
    const float* spl_b1 = (const float*)d_in[15];
    const float* spl_w2 = (const float*)d_in[16];
    const float* spl_b2 = (const float*)d_in[17];
    float* out = (float*)d_out;

    static int smem_set = 0;
    if (!smem_set) {
        cudaFuncSetAttribute(k_out, cudaFuncAttributeMaxDynamicSharedMemorySize, SM_TOTAL);
        smem_set = 1;
    }

    k_embed<<<SEQ, EMB>>>(tag_ids, word_ids, tag_emb, word_emb);
    k_w2pack<<<64, 256>>>(lab_w2);
    k_xpre<<<dim3(49, 2), 1024>>>(wxf, bf, wxb, bb);
    k_lstm<<<16, 512>>>(whf, whb);
    k_uv<<<dim3(193, 2), 256>>>(lab_w1, spl_w1);
    k_out<<<dim3(25, 97), 256, SM_TOTAL>>>(lab_b1, lab_b2, spl_b1, spl_w2, spl_b2, out);
}

// round 13
// speedup vs baseline: 2.4295x; 1.7197x over previous
#include <cuda_runtime.h>
#include <cuda_bf16.h>
#include <cstdint>

#define SEQ 386
#define NP  385
#define HH  256
#define EMB 128
#define G4  1024
#define OSTR (385*129)

typedef unsigned long long ull;

__device__ float g_emb[SEQ][EMB];
__device__ float g_xpre[2][SEQ][G4];
__device__ float g_h[2][SEQ][HH];
__device__ float g_U[NP][HH];
__device__ float g_V[NP][HH];
__device__ ull   g_w2p[256 * 64];   // [k][cpair] packed label w2

__device__ __forceinline__ ull pack2(float lo, float hi) {
    ull r; asm("mov.b64 %0, {%1, %2};" : "=l"(r) : "f"(lo), "f"(hi)); return r;
}
__device__ __forceinline__ void unpack2(ull v, float& lo, float& hi) {
    asm("mov.b64 {%0, %1}, %2;" : "=f"(lo), "=f"(hi) : "l"(v));
}
__device__ __forceinline__ void ffma2(ull& d, ull a, ull b) {
    asm("fma.rn.f32x2 %0, %1, %2, %0;" : "+l"(d) : "l"(a), "l"(b));
}
__device__ __forceinline__ unsigned smem_u32(const void* p) {
    unsigned a;
    asm("{ .reg .u64 t; cvta.to.shared.u64 t, %1; cvt.u32.u64 %0, t; }" : "=r"(a) : "l"(p));
    return a;
}
__device__ __forceinline__ unsigned mapa_rank(unsigned addr, int rank) {
    unsigned ra;
    asm volatile("mapa.shared::cluster.u32 %0, %1, %2;" : "=r"(ra) : "r"(addr), "r"(rank));
    return ra;
}
__device__ __forceinline__ void st_remote(unsigned addr, float v) {
    asm volatile("st.shared::cluster.f32 [%0], %1;" :: "r"(addr), "f"(v) : "memory");
}
__device__ __forceinline__ void cluster_sync_() {
    asm volatile("barrier.cluster.arrive.aligned;" ::: "memory");
    asm volatile("barrier.cluster.wait.aligned;" ::: "memory");
}
__device__ __forceinline__ float sigx(float x)  { return __fdividef(1.f, 1.f + __expf(-x)); }
__device__ __forceinline__ float tanhx(float x) { return 2.f * __fdividef(1.f, 1.f + __expf(-2.f * x)) - 1.f; }

// ---------- K1: embeddings ----------
__global__ void k_embed(const int* __restrict__ tg, const int* __restrict__ wd,
                        const float* __restrict__ te, const float* __restrict__ we) {
    int t = blockIdx.x, d = threadIdx.x;
    g_emb[t][d] = te[tg[t] * EMB + d] + we[wd[t] * EMB + d];
}

// ---------- K1b: pack label w2 ----------
__global__ void k_w2pack(const float* __restrict__ lab_w2) {
    int idx = blockIdx.x * 256 + threadIdx.x;
    int cp = idx >> 8, k = idx & 255;
    g_w2p[k * 64 + cp] = pack2(lab_w2[(2 * cp) * 256 + k], lab_w2[(2 * cp + 1) * 256 + k]);
}

// ---------- K2: x preactivations ----------
__global__ void __launch_bounds__(1024, 1)
k_xpre(const float* __restrict__ wxf, const float* __restrict__ bfp,
       const float* __restrict__ wxb, const float* __restrict__ bbp) {
    __shared__ float se[8][128];
    __shared__ float wt[1024][9];
    int tid = threadIdx.x, t0 = blockIdx.x * 8, dir = blockIdx.y;
    {
        int tp = tid >> 7, d = tid & 127, t = t0 + tp;
        se[tp][d] = (t < SEQ) ? g_emb[t][d] : 0.f;
    }
    const float* Wx = dir ? wxb : wxf;
    const float* bp = dir ? bbp : bfp;
    float acc[8] = {0, 0, 0, 0, 0, 0, 0, 0};
    for (int d0 = 0; d0 < 128; d0 += 8) {
        __syncthreads();
#pragma unroll
        for (int it = 0; it < 8; ++it) {
            int idx = tid + it * 1024;
            int row = idx >> 3, dd = idx & 7;
            wt[row][dd] = Wx[row * 128 + d0 + dd];
        }
        __syncthreads();
#pragma unroll
        for (int dd = 0; dd < 8; ++dd) {
            float w = wt[tid][dd];
#pragma unroll
            for (int tp = 0; tp < 8; ++tp) acc[tp] += w * se[tp][d0 + dd];
        }
    }
    float bias = bp[tid];
#pragma unroll
    for (int tp = 0; tp < 8; ++tp) {
        int t = t0 + tp;
        if (t < SEQ) g_xpre[dir][t][tid] = acc[tp] + bias;
    }
}

// ---------- K3: BiLSTM, cluster.sync + distributed fan-out ----------
__global__ void __cluster_dims__(8, 1, 1) __launch_bounds__(512, 1)
k_lstm(const float* __restrict__ whf, const float* __restrict__ whb) {
    __shared__ __align__(16) float hbuf[2][HH];
    __shared__ __align__(16) float stag[32];
    int tid = threadIdx.x;
    int dir = blockIdx.x >> 3, rank = blockIdx.x & 7;
    int ql = tid >> 4, gt = (tid >> 2) & 3, p = tid & 3, lane = tid & 31;
    int row = gt * 256 + rank * 32 + ql;
    const float* Wh = dir ? whb : whf;

    // register-resident Wh slice, laid out for 16 x LDS.128 of h
    ull wA[16], wB[16];
#pragma unroll
    for (int m = 0; m < 16; ++m) {
        int base = (p << 6) | ((4 * m + 8 * p) & 63);
        const float* wp = Wh + row * 256 + base;
        wA[m] = pack2(wp[0], wp[1]);
        wB[m] = pack2(wp[2], wp[3]);
    }
    ((float*)hbuf)[tid] = 0.f;   // zero both 256-float buffers

    // fan-out addresses: thread (q = tid>>3, r = tid&7) pushes stag[q] to CTA r
    unsigned dst0 = 0, dst1 = 0;
    int fq = tid >> 3, fr = tid & 7;
    if (tid < 256) {
        dst0 = mapa_rank(smem_u32(&hbuf[0][rank * 32 + fq]), fr);
        dst1 = mapa_rank(smem_u32(&hbuf[1][rank * 32 + fq]), fr);
    }
    __syncthreads();
    cluster_sync_();

    bool writer = ((lane & 15) == 0);
    float c_state = 0.f;
    int t = dir ? (SEQ - 1) : 0;
    float xcur = g_xpre[dir][t][row];

    for (int s = 0; s < SEQ; ++s) {
        int cur = s & 1;
        int tn = dir ? (SEQ - 2 - s) : (s + 1);
        float xnext = (s < SEQ - 1) ? g_xpre[dir][tn][row] : 0.f;

        ull acc0 = 0ULL, acc1 = 0ULL;
#pragma unroll
        for (int m = 0; m < 16; m += 2) {
            int b0 = (p << 6) | ((4 * m + 8 * p) & 63);
            int b1 = (p << 6) | ((4 * (m + 1) + 8 * p) & 63);
            ulonglong2 h0 = *(const ulonglong2*)&hbuf[cur][b0];
            ulonglong2 h1 = *(const ulonglong2*)&hbuf[cur][b1];
            ffma2(acc0, wA[m], h0.x);
            ffma2(acc1, wB[m], h0.y);
            ffma2(acc0, wA[m + 1], h1.x);
            ffma2(acc1, wB[m + 1], h1.y);
        }
        float a, b, a1, b1v;
        unpack2(acc0, a, b); unpack2(acc1, a1, b1v);
        float r = (a + a1) + (b + b1v);
        r += __shfl_xor_sync(0xffffffffu, r, 1);
        r += __shfl_xor_sync(0xffffffffu, r, 2);
        float pre = r + xcur;

        int base = lane & 16;
        float pi = __shfl_sync(0xffffffffu, pre, base);
        float pf = __shfl_sync(0xffffffffu, pre, base + 4);
        float pg = __shfl_sync(0xffffffffu, pre, base + 8);
        float po = __shfl_sync(0xffffffffu, pre, base + 12);

        if (writer) {
            c_state = sigx(pf) * c_state + sigx(pi) * tanhx(pg);
            float hv = sigx(po) * tanhx(c_state);
            g_h[dir][t][rank * 32 + ql] = hv;
            stag[ql] = hv;
        }
        __syncthreads();   // stag ready; all reads of hbuf[cur] complete

        if (s < SEQ - 1) {
            if (tid < 256) {
                float hv = stag[fq];
                st_remote((cur ? dst0 : dst1), hv);   // write buffer nxt = cur^1
            }
            cluster_sync_();   // arrive.release orders each thread's own remote store
        }
        t = tn;
        xcur = xnext;
    }
    cluster_sync_();
}

// ---------- K4: U/V span transforms ----------
__global__ void __launch_bounds__(256, 1)
k_uv(const float* __restrict__ lab_w1, const float* __restrict__ spl_w1) {
    __shared__ float sh2[512][2];
    int tid = threadIdx.x, k0 = blockIdx.x * 2, which = blockIdx.y;
    for (int idx = tid; idx < 1024; idx += 256) {
        int d = idx >> 1, kk = idx & 1, k = k0 + kk;
        float v = 0.f;
        if (k < NP) v = (d < 256) ? g_h[0][k][d] : -g_h[1][k + 1][d - 256];
        sh2[d][kk] = v;
    }
    __syncthreads();
    const float* w1 = which ? spl_w1 : lab_w1;
    int w = tid >> 5, lane = tid & 31;
    float (*dst)[HH] = which ? g_V : g_U;
#pragma unroll 2
    for (int cx = 0; cx < 32; ++cx) {
        int c = w * 32 + cx;
        const float* wr = w1 + c * 512;
        ull acc = 0ULL;
#pragma unroll
        for (int m = 0; m < 16; ++m) {
            int d = m * 32 + lane;
            float wv = wr[d];
            ffma2(acc, pack2(wv, wv), *(const ull*)&sh2[d][0]);
        }
        float a, b; unpack2(acc, a, b);
#pragma unroll
        for (int off = 16; off; off >>= 1) {
            a += __shfl_xor_sync(0xffffffffu, a, off);
            b += __shfl_xor_sync(0xffffffffu, b, off);
        }
        if (lane == 0) {
            if (k0     < NP) dst[k0    ][c] = a;
            if (k0 + 1 < NP) dst[k0 + 1][c] = b;
        }
    }
}

// ---------- K5: pairwise outputs ----------
#define HIDSTR 260
#define SM_HID   131072
#define SM_LB1   (SM_HID + 64 * HIDSTR * 4)
#define SM_SB1   (SM_LB1 + 1024)
#define SM_SW2   (SM_SB1 + 1024)
#define SM_LB2   (SM_SW2 + 1024)
#define SM_TOTAL (SM_LB2 + 512)

__global__ void __launch_bounds__(256, 1)
k_out(const float* __restrict__ lab_b1, const float* __restrict__ lab_b2,
      const float* __restrict__ spl_b1, const float* __restrict__ spl_w2,
      const float* __restrict__ spl_b2, float* __restrict__ out) {
    extern __shared__ char sm[];
    ull*   W2P  = (ull*)sm;
    float* HID2 = (float*)(sm + SM_HID);
    float* LB1  = (float*)(sm + SM_LB1);
    float* SB1  = (float*)(sm + SM_SB1);
    float* SW2  = (float*)(sm + SM_SW2);
    float* LB2  = (float*)(sm + SM_LB2);
    int tid = threadIdx.x;
    int j0 = blockIdx.x * 16, i0 = blockIdx.y * 4;

    {
        const float4* src = (const float4*)g_w2p;
        float4* dst = (float4*)W2P;
        for (int it = tid; it < 8192; it += 256) dst[it] = src[it];
    }
    LB1[tid] = lab_b1[tid];
    SB1[tid] = spl_b1[tid];
    SW2[tid] = spl_w2[tid];
    if (tid < 128) LB2[tid] = lab_b2[tid];
    __syncthreads();

    int wp = tid >> 5, lane = tid & 31;
    float sb2 = spl_b2[0];
    for (int px = 0; px < 8; ++px) {
        int p = wp * 8 + px;
        int i = i0 + (p >> 4), j = j0 + (p & 15);
        int ic = min(i, NP - 1), jc = min(j, NP - 1);
        const float* Uj = g_U[jc]; const float* Ui = g_U[ic];
        const float* Vj = g_V[jc]; const float* Vi = g_V[ic];
        float sacc = 0.f;
#pragma unroll
        for (int m = 0; m < 8; ++m) {
            int k = m * 32 + lane;
            HID2[p * HIDSTR + k] = fmaxf(Uj[k] - Ui[k] + LB1[k], 0.f);
            sacc += fmaxf(Vj[k] - Vi[k] + SB1[k], 0.f) * SW2[k];
        }
#pragma unroll
        for (int off = 16; off; off >>= 1)
            sacc += __shfl_xor_sync(0xffffffffu, sacc, off);
        if (lane == 0 && i < NP && j < NP)
            out[i * OSTR + j * 129 + 128] = sacc + sb2;
    }
    __syncthreads();

    int pg = tid >> 4, cg = tid & 15;
    ull acc[4][4];
#pragma unroll
    for (int a = 0; a < 4; ++a)
#pragma unroll
        for (int b = 0; b < 4; ++b) acc[a][b] = 0ULL;

    const float* hb = HID2 + pg * 4 * HIDSTR;
    const ull*  wb = W2P + cg;
#pragma unroll 2
    for (int k = 0; k < 256; ++k) {
        float h0 = hb[k], h1 = hb[HIDSTR + k], h2 = hb[2 * HIDSTR + k], h3 = hb[3 * HIDSTR + k];
        ull H0 = pack2(h0, h0), H1 = pack2(h1, h1), H2 = pack2(h2, h2), H3 = pack2(h3, h3);
        ull w0 = wb[k * 64], w1 = wb[k * 64 + 16], w2 = wb[k * 64 + 32], w3 = wb[k * 64 + 48];
        ffma2(acc[0][0], H0, w0); ffma2(acc[0][1], H0, w1); ffma2(acc[0][2], H0, w2); ffma2(acc[0][3], H0, w3);
        ffma2(acc[1][0], H1, w0); ffma2(acc[1][1], H1, w1); ffma2(acc[1][2], H1, w2); ffma2(acc[1][3], H1, w3);
        ffma2(acc[2][0], H2, w0); ffma2(acc[2][1], H2, w1); ffma2(acc[2][2], H2, w2); ffma2(acc[2][3], H2, w3);
        ffma2(acc[3][0], H3, w0); ffma2(acc[3][1], H3, w1); ffma2(acc[3][2], H3, w2); ffma2(acc[3][3], H3, w3);
    }
#pragma unroll
    for (int pp = 0; pp < 4; ++pp) {
        int p = pg * 4 + pp;
        int i = i0 + (p >> 4), j = j0 + (p & 15);
        if (i >= NP || j >= NP) continue;
        float* o = out + i * OSTR + j * 129;
#pragma unroll
        for (int q = 0; q < 4; ++q) {
            int cp = cg + 16 * q;
            float lo, hi; unpack2(acc[pp][q], lo, hi);
            o[2 * cp]     = lo + LB2[2 * cp];
            o[2 * cp + 1] = hi + LB2[2 * cp + 1];
        }
    }
}

extern "C" void kernel_launch(void* const* d_in, const int* in_sizes, int n_in,
                              void* d_out, int out_size) {
    const int*   tag_ids  = (const int*)d_in[0];
    const int*   word_ids = (const int*)d_in[1];
    const float* tag_emb  = (const float*)d_in[2];
    const float* word_emb = (const float*)d_in[3];
    const float* wxf = (const float*)d_in[4];
    const float* whf = (const float*)d_in[5];
    const float* bf  = (const float*)d_in[6];
    const float* wxb = (const float*)d_in[7];
    const float* whb = (const float*)d_in[8];
    const float* bb  = (const float*)d_in[9];
    const float* lab_w1 = (const float*)d_in[10];
    const float* lab_b1 = (const float*)d_in[11];
    const float* lab_w2 = (const float*)d_in[12];
    const float* lab_b2 = (const float*)d_in[13];
    const float* spl_w1 = (const float*)d_in[14];
    const float* spl_b1 = (const float*)d_in[15];
    const float* spl_w2 = (const float*)d_in[16];
    const float* spl_b2 = (const float*)d_in[17];
    float* out = (float*)d_out;

    static int smem_set = 0;
    if (!smem_set) {
        cudaFuncSetAttribute(k_out, cudaFuncAttributeMaxDynamicSharedMemorySize, SM_TOTAL);
        smem_set = 1;
    }

    k_embed<<<SEQ, EMB>>>(tag_ids, word_ids, tag_emb, word_emb);
    k_w2pack<<<64, 256>>>(lab_w2);
    k_xpre<<<dim3(49, 2), 1024>>>(wxf, bf, wxb, bb);
    k_lstm<<<16, 512>>>(whf, whb);
    k_uv<<<dim3(193, 2), 256>>>(lab_w1, spl_w1);
    k_out<<<dim3(25, 97), 256, SM_TOTAL>>>(lab_b1, lab_b2, spl_b1, spl_w2, spl_b2, out);
}

// round 14
// speedup vs baseline: 2.6416x; 1.0873x over previous
#include <cuda_runtime.h>
#include <cuda_bf16.h>
#include <cstdint>

#define SEQ 386
#define NP  385
#define HH  256
#define EMB 128
#define G4  1024
#define OSTR (385*129)

typedef unsigned long long ull;

__device__ float g_emb[SEQ][EMB];
__device__ float g_xpre[2][SEQ][G4];
__device__ float g_h[2][SEQ][HH];
__device__ float g_U[NP][HH];
__device__ float g_V[NP][HH];
__device__ ull   g_w2p[256 * 64];   // [k][cpair] packed label w2

__device__ __forceinline__ ull pack2(float lo, float hi) {
    ull r; asm("mov.b64 %0, {%1, %2};" : "=l"(r) : "f"(lo), "f"(hi)); return r;
}
__device__ __forceinline__ void unpack2(ull v, float& lo, float& hi) {
    asm("mov.b64 {%0, %1}, %2;" : "=f"(lo), "=f"(hi) : "l"(v));
}
__device__ __forceinline__ void ffma2(ull& d, ull a, ull b) {
    asm("fma.rn.f32x2 %0, %1, %2, %0;" : "+l"(d) : "l"(a), "l"(b));
}
__device__ __forceinline__ unsigned smem_u32(const void* p) {
    unsigned a;
    asm("{ .reg .u64 t; cvta.to.shared.u64 t, %1; cvt.u32.u64 %0, t; }" : "=r"(a) : "l"(p));
    return a;
}
__device__ __forceinline__ unsigned mapa_rank(unsigned addr, int rank) {
    unsigned ra;
    asm volatile("mapa.shared::cluster.u32 %0, %1, %2;" : "=r"(ra) : "r"(addr), "r"(rank));
    return ra;
}
__device__ __forceinline__ void mbar_init(unsigned addr, unsigned cnt) {
    asm volatile("mbarrier.init.shared.b64 [%0], %1;" :: "r"(addr), "r"(cnt) : "memory");
}
__device__ __forceinline__ void mbar_expect_tx(unsigned addr, unsigned bytes) {
    asm volatile("mbarrier.arrive.expect_tx.shared.b64 _, [%0], %1;"
                 :: "r"(addr), "r"(bytes) : "memory");
}
__device__ __forceinline__ void mbar_wait(unsigned addr, unsigned parity) {
    asm volatile(
        "{\n\t.reg .pred P;\n\t"
        "LW_%=:\n\t"
        "mbarrier.try_wait.parity.acquire.cluster.shared::cta.b64 P, [%0], %1, 0x989680;\n\t"
        "@P bra.uni LD_%=;\n\t"
        "bra.uni LW_%=;\n\t"
        "LD_%=:\n\t}"
        :: "r"(addr), "r"(parity) : "memory");
}
__device__ __forceinline__ void bulk_s2s(unsigned dst, unsigned src, unsigned bytes, unsigned rbar) {
    asm volatile(
        "cp.async.bulk.shared::cluster.shared::cta.mbarrier::complete_tx::bytes [%0], [%1], %2, [%3];"
        :: "r"(dst), "r"(src), "r"(bytes), "r"(rbar) : "memory");
}
__device__ __forceinline__ void fence_async_() {
    asm volatile("fence.proxy.async.shared::cta;" ::: "memory");
}
__device__ __forceinline__ void cluster_sync_() {
    asm volatile("barrier.cluster.arrive.aligned;" ::: "memory");
    asm volatile("barrier.cluster.wait.aligned;" ::: "memory");
}
__device__ __forceinline__ float sigx(float x)  { return __fdividef(1.f, 1.f + __expf(-x)); }
__device__ __forceinline__ float tanhx(float x) { return 2.f * __fdividef(1.f, 1.f + __expf(-2.f * x)) - 1.f; }

// ---------- K1: embeddings ----------
__global__ void k_embed(const int* __restrict__ tg, const int* __restrict__ wd,
                        const float* __restrict__ te, const float* __restrict__ we) {
    int t = blockIdx.x, d = threadIdx.x;
    g_emb[t][d] = te[tg[t] * EMB + d] + we[wd[t] * EMB + d];
}

// ---------- K1b: pack label w2 ----------
__global__ void k_w2pack(const float* __restrict__ lab_w2) {
    int idx = blockIdx.x * 256 + threadIdx.x;
    int cp = idx >> 8, k = idx & 255;
    g_w2p[k * 64 + cp] = pack2(lab_w2[(2 * cp) * 256 + k], lab_w2[(2 * cp + 1) * 256 + k]);
}

// ---------- K2: x preactivations ----------
__global__ void __launch_bounds__(1024, 1)
k_xpre(const float* __restrict__ wxf, const float* __restrict__ bfp,
       const float* __restrict__ wxb, const float* __restrict__ bbp) {
    __shared__ float se[8][128];
    __shared__ float wt[1024][9];
    int tid = threadIdx.x, t0 = blockIdx.x * 8, dir = blockIdx.y;
    {
        int tp = tid >> 7, d = tid & 127, t = t0 + tp;
        se[tp][d] = (t < SEQ) ? g_emb[t][d] : 0.f;
    }
    const float* Wx = dir ? wxb : wxf;
    const float* bp = dir ? bbp : bfp;
    float acc[8] = {0, 0, 0, 0, 0, 0, 0, 0};
    for (int d0 = 0; d0 < 128; d0 += 8) {
        __syncthreads();
#pragma unroll
        for (int it = 0; it < 8; ++it) {
            int idx = tid + it * 1024;
            int row = idx >> 3, dd = idx & 7;
            wt[row][dd] = Wx[row * 128 + d0 + dd];
        }
        __syncthreads();
#pragma unroll
        for (int dd = 0; dd < 8; ++dd) {
            float w = wt[tid][dd];
#pragma unroll
            for (int tp = 0; tp < 8; ++tp) acc[tp] += w * se[tp][d0 + dd];
        }
    }
    float bias = bp[tid];
#pragma unroll
    for (int tp = 0; tp < 8; ++tp) {
        int t = t0 + tp;
        if (t < SEQ) g_xpre[dir][t][tid] = acc[tp] + bias;
    }
}

// ---------- K3: BiLSTM, bulk-copy + tx-mbarrier pipeline, 8-CTA cluster/dir ----------
__global__ void __cluster_dims__(8, 1, 1) __launch_bounds__(512, 1)
k_lstm(const float* __restrict__ whf, const float* __restrict__ whb) {
    __shared__ __align__(16) float hbuf[2][HH];
    __shared__ __align__(16) float stag[2][32];
    __shared__ __align__(8) ull mbar[2];
    int tid = threadIdx.x;
    int dir = blockIdx.x >> 3, rank = blockIdx.x & 7;
    int ql = tid >> 4, gt = (tid >> 2) & 3, p = tid & 3, lane = tid & 31;
    int row = gt * 256 + rank * 32 + ql;
    const float* Wh = dir ? whb : whf;

    // register-resident Wh slice, laid out for 16 x LDS.128 of h
    ull wA[16], wB[16];
#pragma unroll
    for (int m = 0; m < 16; ++m) {
        int base = (p << 6) | ((4 * m + 8 * p) & 63);
        const float* wp = Wh + row * 256 + base;
        wA[m] = pack2(wp[0], wp[1]);
        wB[m] = pack2(wp[2], wp[3]);
    }
    ((float*)hbuf)[tid] = 0.f;   // zero both 256-float buffers

    unsigned mb0 = smem_u32(&mbar[0]), mb1 = smem_u32(&mbar[1]);
    if (tid == 0) {
        mbar_init(mb0, 1);
        mbar_init(mb1, 1);
        mbar_expect_tx(mb0, 1024);   // arm phase 0 of both buffers
        mbar_expect_tx(mb1, 1024);
    }
    // per-issuing-thread precomputed addresses (tid<8: dest rank = tid)
    unsigned dstB0 = 0, dstB1 = 0, rbar0 = 0, rbar1 = 0;
    if (tid < 8) {
        dstB0 = mapa_rank(smem_u32(&hbuf[0][rank * 32]), tid);
        dstB1 = mapa_rank(smem_u32(&hbuf[1][rank * 32]), tid);
        rbar0 = mapa_rank(mb0, tid);
        rbar1 = mapa_rank(mb1, tid);
    }
    unsigned srcS0 = smem_u32(&stag[0][0]), srcS1 = smem_u32(&stag[1][0]);
    __syncthreads();
    cluster_sync_();   // all mbarriers initialized+armed before any copy

    unsigned ph0 = 0, ph1 = 0;
    bool writer = ((lane & 15) == 0);
    float c_state = 0.f;
    int t = dir ? (SEQ - 1) : 0;
    float xcur = g_xpre[dir][t][row];

    for (int s = 0; s < SEQ; ++s) {
        int cur = s & 1, nxt = cur ^ 1;
        int tn = dir ? (SEQ - 2 - s) : (s + 1);
        float xnext = (s < SEQ - 1) ? g_xpre[dir][tn][row] : 0.f;

        if (s) {   // wait incoming h for this step (8 x 128B tx + 1 arm)
            if (cur) { mbar_wait(mb1, ph1); ph1 ^= 1; }
            else     { mbar_wait(mb0, ph0); ph0 ^= 1; }
        }

        ull acc0 = 0ULL, acc1 = 0ULL;
#pragma unroll
        for (int m = 0; m < 16; m += 2) {
            int b0 = (p << 6) | ((4 * m + 8 * p) & 63);
            int b1 = (p << 6) | ((4 * (m + 1) + 8 * p) & 63);
            ulonglong2 h0 = *(const ulonglong2*)&hbuf[cur][b0];
            ulonglong2 h1 = *(const ulonglong2*)&hbuf[cur][b1];
            ffma2(acc0, wA[m], h0.x);
            ffma2(acc1, wB[m], h0.y);
            ffma2(acc0, wA[m + 1], h1.x);
            ffma2(acc1, wB[m + 1], h1.y);
        }
        float a, b, a1, b1v;
        unpack2(acc0, a, b); unpack2(acc1, a1, b1v);
        float r = (a + a1) + (b + b1v);
        r += __shfl_xor_sync(0xffffffffu, r, 1);
        r += __shfl_xor_sync(0xffffffffu, r, 2);
        float pre = r + xcur;

        int base = lane & 16;
        float pi = __shfl_sync(0xffffffffu, pre, base);
        float pf = __shfl_sync(0xffffffffu, pre, base + 4);
        float pg = __shfl_sync(0xffffffffu, pre, base + 8);
        float po = __shfl_sync(0xffffffffu, pre, base + 12);

        if (writer) {
            c_state = sigx(pf) * c_state + sigx(pi) * tanhx(pg);
            float hv = sigx(po) * tanhx(c_state);
            g_h[dir][t][rank * 32 + ql] = hv;
            stag[cur][ql] = hv;
        }
        __syncthreads();   // stag ready; all reads of hbuf[cur] complete

        if (s && tid == 0) {   // re-arm the just-consumed buffer for step s+2
            mbar_expect_tx(cur ? mb1 : mb0, 1024);
        }
        if (s < SEQ - 1 && tid < 8) {
            fence_async_();    // make generic stag writes visible to async proxy
            bulk_s2s(cur ? dstB0 : dstB1,          // write buffer nxt
                     cur ? srcS1 : srcS0,          // src = stag[cur]
                     128,
                     cur ? rbar0 : rbar1);         // remote mbar[nxt]
        }
        t = tn;
        xcur = xnext;
    }
    cluster_sync_();
}

// ---------- K4: U/V span transforms ----------
__global__ void __launch_bounds__(256, 1)
k_uv(const float* __restrict__ lab_w1, const float* __restrict__ spl_w1) {
    __shared__ float sh2[512][2];
    int tid = threadIdx.x, k0 = blockIdx.x * 2, which = blockIdx.y;
    for (int idx = tid; idx < 1024; idx += 256) {
        int d = idx >> 1, kk = idx & 1, k = k0 + kk;
        float v = 0.f;
        if (k < NP) v = (d < 256) ? g_h[0][k][d] : -g_h[1][k + 1][d - 256];
        sh2[d][kk] = v;
    }
    __syncthreads();
    const float* w1 = which ? spl_w1 : lab_w1;
    int w = tid >> 5, lane = tid & 31;
    float (*dst)[HH] = which ? g_V : g_U;
#pragma unroll 2
    for (int cx = 0; cx < 32; ++cx) {
        int c = w * 32 + cx;
        const float* wr = w1 + c * 512;
        ull acc = 0ULL;
#pragma unroll
        for (int m = 0; m < 16; ++m) {
            int d = m * 32 + lane;
            float wv = wr[d];
            ffma2(acc, pack2(wv, wv), *(const ull*)&sh2[d][0]);
        }
        float a, b; unpack2(acc, a, b);
#pragma unroll
        for (int off = 16; off; off >>= 1) {
            a += __shfl_xor_sync(0xffffffffu, a, off);
            b += __shfl_xor_sync(0xffffffffu, b, off);
        }
        if (lane == 0) {
            if (k0     < NP) dst[k0    ][c] = a;
            if (k0 + 1 < NP) dst[k0 + 1][c] = b;
        }
    }
}

// ---------- K5: pairwise outputs ----------
#define HIDSTR 260
#define SM_HID   131072
#define SM_LB1   (SM_HID + 64 * HIDSTR * 4)
#define SM_SB1   (SM_LB1 + 1024)
#define SM_SW2   (SM_SB1 + 1024)
#define SM_LB2   (SM_SW2 + 1024)
#define SM_TOTAL (SM_LB2 + 512)

__global__ void __launch_bounds__(256, 1)
k_out(const float* __restrict__ lab_b1, const float* __restrict__ lab_b2,
      const float* __restrict__ spl_b1, const float* __restrict__ spl_w2,
      const float* __restrict__ spl_b2, float* __restrict__ out) {
    extern __shared__ char sm[];
    ull*   W2P  = (ull*)sm;
    float* HID2 = (float*)(sm + SM_HID);
    float* LB1  = (float*)(sm + SM_LB1);
    float* SB1  = (float*)(sm + SM_SB1);
    float* SW2  = (float*)(sm + SM_SW2);
    float* LB2  = (float*)(sm + SM_LB2);
    int tid = threadIdx.x;
    int j0 = blockIdx.x * 16, i0 = blockIdx.y * 4;

    {
        const float4* src = (const float4*)g_w2p;
        float4* dst = (float4*)W2P;
        for (int it = tid; it < 8192; it += 256) dst[it] = src[it];
    }
    LB1[tid] = lab_b1[tid];
    SB1[tid] = spl_b1[tid];
    SW2[tid] = spl_w2[tid];
    if (tid < 128) LB2[tid] = lab_b2[tid];
    __syncthreads();

    int wp = tid >> 5, lane = tid & 31;
    float sb2 = spl_b2[0];
    for (int px = 0; px < 8; ++px) {
        int p = wp * 8 + px;
        int i = i0 + (p >> 4), j = j0 + (p & 15);
        int ic = min(i, NP - 1), jc = min(j, NP - 1);
        const float* Uj = g_U[jc]; const float* Ui = g_U[ic];
        const float* Vj = g_V[jc]; const float* Vi = g_V[ic];
        float sacc = 0.f;
#pragma unroll
        for (int m = 0; m < 8; ++m) {
            int k = m * 32 + lane;
            HID2[p * HIDSTR + k] = fmaxf(Uj[k] - Ui[k] + LB1[k], 0.f);
            sacc += fmaxf(Vj[k] - Vi[k] + SB1[k], 0.f) * SW2[k];
        }
#pragma unroll
        for (int off = 16; off; off >>= 1)
            sacc += __shfl_xor_sync(0xffffffffu, sacc, off);
        if (lane == 0 && i < NP && j < NP)
            out[i * OSTR + j * 129 + 128] = sacc + sb2;
    }
    __syncthreads();

    int pg = tid >> 4, cg = tid & 15;
    ull acc[4][4];
#pragma unroll
    for (int a = 0; a < 4; ++a)
#pragma unroll
        for (int b = 0; b < 4; ++b) acc[a][b] = 0ULL;

    const float* hb = HID2 + pg * 4 * HIDSTR;
    const ull*  wb = W2P + cg;
#pragma unroll 2
    for (int k = 0; k < 256; ++k) {
        float h0 = hb[k], h1 = hb[HIDSTR + k], h2 = hb[2 * HIDSTR + k], h3 = hb[3 * HIDSTR + k];
        ull H0 = pack2(h0, h0), H1 = pack2(h1, h1), H2 = pack2(h2, h2), H3 = pack2(h3, h3);
        ull w0 = wb[k * 64], w1 = wb[k * 64 + 16], w2 = wb[k * 64 + 32], w3 = wb[k * 64 + 48];
        ffma2(acc[0][0], H0, w0); ffma2(acc[0][1], H0, w1); ffma2(acc[0][2], H0, w2); ffma2(acc[0][3], H0, w3);
        ffma2(acc[1][0], H1, w0); ffma2(acc[1][1], H1, w1); ffma2(acc[1][2], H1, w2); ffma2(acc[1][3], H1, w3);
        ffma2(acc[2][0], H2, w0); ffma2(acc[2][1], H2, w1); ffma2(acc[2][2], H2, w2); ffma2(acc[2][3], H2, w3);
        ffma2(acc[3][0], H3, w0); ffma2(acc[3][1], H3, w1); ffma2(acc[3][2], H3, w2); ffma2(acc[3][3], H3, w3);
    }
#pragma unroll
    for (int pp = 0; pp < 4; ++pp) {
        int p = pg * 4 + pp;
        int i = i0 + (p >> 4), j = j0 + (p & 15);
        if (i >= NP || j >= NP) continue;
        float* o = out + i * OSTR + j * 129;
#pragma unroll
        for (int q = 0; q < 4; ++q) {
            int cp = cg + 16 * q;
            float lo, hi; unpack2(acc[pp][q], lo, hi);
            o[2 * cp]     = lo + LB2[2 * cp];
            o[2 * cp + 1] = hi + LB2[2 * cp + 1];
        }
    }
}

extern "C" void kernel_launch(void* const* d_in, const int* in_sizes, int n_in,
                              void* d_out, int out_size) {
    const int*   tag_ids  = (const int*)d_in[0];
    const int*   word_ids = (const int*)d_in[1];
    const float* tag_emb  = (const float*)d_in[2];
    const float* word_emb = (const float*)d_in[3];
    const float* wxf = (const float*)d_in[4];
    const float* whf = (const float*)d_in[5];
    const float* bf  = (const float*)d_in[6];
    const float* wxb = (const float*)d_in[7];
    const float* whb = (const float*)d_in[8];
    const float* bb  = (const float*)d_in[9];
    const float* lab_w1 = (const float*)d_in[10];
    const float* lab_b1 = (const float*)d_in[11];
    const float* lab_w2 = (const float*)d_in[12];
    const float* lab_b2 = (const float*)d_in[13];
    const float* spl_w1 = (const float*)d_in[14];
    const float* spl_b1 = (const float*)d_in[15];
    const float* spl_w2 = (const float*)d_in[16];
    const float* spl_b2 = (const float*)d_in[17];
    float* out = (float*)d_out;

    static int smem_set = 0;
    if (!smem_set) {
        cudaFuncSetAttribute(k_out, cudaFuncAttributeMaxDynamicSharedMemorySize, SM_TOTAL);
        smem_set = 1;
    }

    k_embed<<<SEQ, EMB>>>(tag_ids, word_ids, tag_emb, word_emb);
    k_w2pack<<<64, 256>>>(lab_w2);
    k_xpre<<<dim3(49, 2), 1024>>>(wxf, bf, wxb, bb);
    k_lstm<<<16, 512>>>(whf, whb);
    k_uv<<<dim3(193, 2), 256>>>(lab_w1, spl_w1);
    k_out<<<dim3(25, 97), 256, SM_TOTAL>>>(lab_b1, lab_b2, spl_b1, spl_w2, spl_b2, out);
}

// round 15
// speedup vs baseline: 2.7475x; 1.0401x over previous
#include <cuda_runtime.h>
#include <cuda_bf16.h>
#include <cstdint>

#define SEQ 386
#define NP  385
#define HH  256
#define EMB 128
#define G4  1024
#define OSTR (385*129)

typedef unsigned long long ull;

__device__ float g_emb[SEQ][EMB];
__device__ float g_xpre[2][SEQ][G4];
__device__ float g_h[2][SEQ][HH];
__device__ float g_U[NP][HH];
__device__ float g_V[NP][HH];
__device__ ull   g_w2p[256 * 64];   // [k][cpair] packed label w2

__device__ __forceinline__ ull pack2(float lo, float hi) {
    ull r; asm("mov.b64 %0, {%1, %2};" : "=l"(r) : "f"(lo), "f"(hi)); return r;
}
__device__ __forceinline__ void unpack2(ull v, float& lo, float& hi) {
    asm("mov.b64 {%0, %1}, %2;" : "=f"(lo), "=f"(hi) : "l"(v));
}
__device__ __forceinline__ void ffma2(ull& d, ull a, ull b) {
    asm("fma.rn.f32x2 %0, %1, %2, %0;" : "+l"(d) : "l"(a), "l"(b));
}
__device__ __forceinline__ unsigned smem_u32(const void* p) {
    unsigned a;
    asm("{ .reg .u64 t; cvta.to.shared.u64 t, %1; cvt.u32.u64 %0, t; }" : "=r"(a) : "l"(p));
    return a;
}
__device__ __forceinline__ unsigned mapa_rank(unsigned addr, int rank) {
    unsigned ra;
    asm volatile("mapa.shared::cluster.u32 %0, %1, %2;" : "=r"(ra) : "r"(addr), "r"(rank));
    return ra;
}
__device__ __forceinline__ void mbar_init(unsigned addr, unsigned cnt) {
    asm volatile("mbarrier.init.shared.b64 [%0], %1;" :: "r"(addr), "r"(cnt) : "memory");
}
__device__ __forceinline__ void mbar_expect_tx(unsigned addr, unsigned bytes) {
    asm volatile("mbarrier.arrive.expect_tx.shared.b64 _, [%0], %1;"
                 :: "r"(addr), "r"(bytes) : "memory");
}
__device__ __forceinline__ void mbar_wait(unsigned addr, unsigned parity) {
    asm volatile(
        "{\n\t.reg .pred P;\n\t"
        "LW_%=:\n\t"
        "mbarrier.try_wait.parity.acquire.cluster.shared::cta.b64 P, [%0], %1, 0x989680;\n\t"
        "@P bra.uni LD_%=;\n\t"
        "bra.uni LW_%=;\n\t"
        "LD_%=:\n\t}"
        :: "r"(addr), "r"(parity) : "memory");
}
__device__ __forceinline__ void st_async_b64(unsigned addr, ull v, unsigned mbar) {
    asm volatile("st.async.shared::cluster.mbarrier::complete_tx::bytes.b64 [%0], %1, [%2];"
                 :: "r"(addr), "l"(v), "r"(mbar) : "memory");
}
__device__ __forceinline__ void cluster_sync_() {
    asm volatile("barrier.cluster.arrive.aligned;" ::: "memory");
    asm volatile("barrier.cluster.wait.aligned;" ::: "memory");
}
__device__ __forceinline__ float sigx(float x)  { return __fdividef(1.f, 1.f + __expf(-x)); }
__device__ __forceinline__ float tanhx(float x) { return 2.f * __fdividef(1.f, 1.f + __expf(-2.f * x)) - 1.f; }

// ---------- K1: embeddings ----------
__global__ void k_embed(const int* __restrict__ tg, const int* __restrict__ wd,
                        const float* __restrict__ te, const float* __restrict__ we) {
    int t = blockIdx.x, d = threadIdx.x;
    g_emb[t][d] = te[tg[t] * EMB + d] + we[wd[t] * EMB + d];
}

// ---------- K1b: pack label w2 ----------
__global__ void k_w2pack(const float* __restrict__ lab_w2) {
    int idx = blockIdx.x * 256 + threadIdx.x;
    int cp = idx >> 8, k = idx & 255;
    g_w2p[k * 64 + cp] = pack2(lab_w2[(2 * cp) * 256 + k], lab_w2[(2 * cp + 1) * 256 + k]);
}

// ---------- K2: x preactivations ----------
__global__ void __launch_bounds__(1024, 1)
k_xpre(const float* __restrict__ wxf, const float* __restrict__ bfp,
       const float* __restrict__ wxb, const float* __restrict__ bbp) {
    __shared__ float se[8][128];
    __shared__ float wt[1024][9];
    int tid = threadIdx.x, t0 = blockIdx.x * 8, dir = blockIdx.y;
    {
        int tp = tid >> 7, d = tid & 127, t = t0 + tp;
        se[tp][d] = (t < SEQ) ? g_emb[t][d] : 0.f;
    }
    const float* Wx = dir ? wxb : wxf;
    const float* bp = dir ? bbp : bfp;
    float acc[8] = {0, 0, 0, 0, 0, 0, 0, 0};
    for (int d0 = 0; d0 < 128; d0 += 8) {
        __syncthreads();
#pragma unroll
        for (int it = 0; it < 8; ++it) {
            int idx = tid + it * 1024;
            int row = idx >> 3, dd = idx & 7;
            wt[row][dd] = Wx[row * 128 + d0 + dd];
        }
        __syncthreads();
#pragma unroll
        for (int dd = 0; dd < 8; ++dd) {
            float w = wt[tid][dd];
#pragma unroll
            for (int tp = 0; tp < 8; ++tp) acc[tp] += w * se[tp][d0 + dd];
        }
    }
    float bias = bp[tid];
#pragma unroll
    for (int tp = 0; tp < 8; ++tp) {
        int t = t0 + tp;
        if (t < SEQ) g_xpre[dir][t][tid] = acc[tp] + bias;
    }
}

// ---------- K3: BiLSTM, st.async direct scatter + tx-mbarrier, 8-CTA cluster/dir ----------
__global__ void __cluster_dims__(8, 1, 1) __launch_bounds__(512, 1)
k_lstm(const float* __restrict__ whf, const float* __restrict__ whb) {
    __shared__ __align__(16) float hbuf[2][HH];
    __shared__ __align__(8) ull mbar[2];
    int tid = threadIdx.x;
    int dir = blockIdx.x >> 3, rank = blockIdx.x & 7;
    int ql = tid >> 4, gt = (tid >> 2) & 3, p = tid & 3, lane = tid & 31;
    int wid = tid >> 5;
    int row = gt * 256 + rank * 32 + ql;
    const float* Wh = dir ? whb : whf;

    // register-resident Wh slice, laid out for 16 x LDS.128 of h
    ull wA[16], wB[16];
#pragma unroll
    for (int m = 0; m < 16; ++m) {
        int base = (p << 6) | ((4 * m + 8 * p) & 63);
        const float* wp = Wh + row * 256 + base;
        wA[m] = pack2(wp[0], wp[1]);
        wB[m] = pack2(wp[2], wp[3]);
    }
    ((float*)hbuf)[tid] = 0.f;   // zero both 256-float buffers

    unsigned mb0 = smem_u32(&mbar[0]), mb1 = smem_u32(&mbar[1]);
    if (tid == 0) {
        mbar_init(mb0, 1);
        mbar_init(mb1, 1);
        mbar_expect_tx(mb0, 1024);   // phase-0 arms for both buffers
        mbar_expect_tx(mb1, 1024);
    }
    // lane0-of-warp scatter addresses: pair (2*wid, 2*wid+1) at offset rank*32+2*wid
    unsigned hoff = smem_u32(&hbuf[0][rank * 32 + 2 * wid]);
    __syncthreads();
    cluster_sync_();   // all mbarriers initialized+armed before any store

    unsigned ph0 = 0, ph1 = 0;
    bool writer = ((lane & 15) == 0);
    float c_state = 0.f;
    int t = dir ? (SEQ - 1) : 0;
    float xcur = g_xpre[dir][t][row];

    for (int s = 0; s < SEQ; ++s) {
        int cur = s & 1, nxt = cur ^ 1;
        int tn = dir ? (SEQ - 2 - s) : (s + 1);
        float xnext = (s < SEQ - 1) ? g_xpre[dir][tn][row] : 0.f;

        if (s) {   // wait incoming h for this step (128 b64 tx + 1 arm = 1024B)
            if (cur) { mbar_wait(mb1, ph1); ph1 ^= 1; }
            else     { mbar_wait(mb0, ph0); ph0 ^= 1; }
            if (tid == 0) mbar_expect_tx(cur ? mb1 : mb0, 1024);  // re-arm for s+2
        }
        __syncthreads();   // arm ordered before any of this CTA's stores this step

        ull acc0 = 0ULL, acc1 = 0ULL;
#pragma unroll
        for (int m = 0; m < 16; m += 2) {
            int b0 = (p << 6) | ((4 * m + 8 * p) & 63);
            int b1 = (p << 6) | ((4 * (m + 1) + 8 * p) & 63);
            ulonglong2 h0 = *(const ulonglong2*)&hbuf[cur][b0];
            ulonglong2 h1 = *(const ulonglong2*)&hbuf[cur][b1];
            ffma2(acc0, wA[m], h0.x);
            ffma2(acc1, wB[m], h0.y);
            ffma2(acc0, wA[m + 1], h1.x);
            ffma2(acc1, wB[m + 1], h1.y);
        }
        float a, b, a1, b1v;
        unpack2(acc0, a, b); unpack2(acc1, a1, b1v);
        float r = (a + a1) + (b + b1v);
        r += __shfl_xor_sync(0xffffffffu, r, 1);
        r += __shfl_xor_sync(0xffffffffu, r, 2);
        float pre = r + xcur;

        int base = lane & 16;
        float pi = __shfl_sync(0xffffffffu, pre, base);
        float pf = __shfl_sync(0xffffffffu, pre, base + 4);
        float pg = __shfl_sync(0xffffffffu, pre, base + 8);
        float po = __shfl_sync(0xffffffffu, pre, base + 12);

        float hv = 0.f;
        if (writer) {
            c_state = sigx(pf) * c_state + sigx(pi) * tanhx(pg);
            hv = sigx(po) * tanhx(c_state);
            g_h[dir][t][rank * 32 + ql] = hv;
        }
        // pair the two writer lanes (0,16): lane0 sends b64 {h[2w], h[2w+1]}
        float hvB = __shfl_sync(0xffffffffu, hv, 16);
        if (lane == 0 && s < SEQ - 1) {
            ull hp = pack2(hv, hvB);
            unsigned hdst = hoff + (unsigned)(nxt * 1024);   // hbuf[nxt][...]
            unsigned mbl  = nxt ? mb1 : mb0;
#pragma unroll
            for (int rr = 0; rr < 8; ++rr) {
                unsigned d  = mapa_rank(hdst, rr);
                unsigned mr = mapa_rank(mbl, rr);
                st_async_b64(d, hp, mr);
            }
        }
        t = tn;
        xcur = xnext;
    }
    cluster_sync_();
}

// ---------- K4: U/V span transforms ----------
__global__ void __launch_bounds__(256, 1)
k_uv(const float* __restrict__ lab_w1, const float* __restrict__ spl_w1) {
    __shared__ float sh2[512][2];
    int tid = threadIdx.x, k0 = blockIdx.x * 2, which = blockIdx.y;
    for (int idx = tid; idx < 1024; idx += 256) {
        int d = idx >> 1, kk = idx & 1, k = k0 + kk;
        float v = 0.f;
        if (k < NP) v = (d < 256) ? g_h[0][k][d] : -g_h[1][k + 1][d - 256];
        sh2[d][kk] = v;
    }
    __syncthreads();
    const float* w1 = which ? spl_w1 : lab_w1;
    int w = tid >> 5, lane = tid & 31;
    float (*dst)[HH] = which ? g_V : g_U;
#pragma unroll 2
    for (int cx = 0; cx < 32; ++cx) {
        int c = w * 32 + cx;
        const float* wr = w1 + c * 512;
        ull acc = 0ULL;
#pragma unroll
        for (int m = 0; m < 16; ++m) {
            int d = m * 32 + lane;
            float wv = wr[d];
            ffma2(acc, pack2(wv, wv), *(const ull*)&sh2[d][0]);
        }
        float a, b; unpack2(acc, a, b);
#pragma unroll
        for (int off = 16; off; off >>= 1) {
            a += __shfl_xor_sync(0xffffffffu, a, off);
            b += __shfl_xor_sync(0xffffffffu, b, off);
        }
        if (lane == 0) {
            if (k0     < NP) dst[k0    ][c] = a;
            if (k0 + 1 < NP) dst[k0 + 1][c] = b;
        }
    }
}

// ---------- K5: pairwise outputs ----------
#define HIDSTR 260
#define SM_HID   131072
#define SM_LB1   (SM_HID + 64 * HIDSTR * 4)
#define SM_SB1   (SM_LB1 + 1024)
#define SM_SW2   (SM_SB1 + 1024)
#define SM_LB2   (SM_SW2 + 1024)
#define SM_TOTAL (SM_LB2 + 512)

__global__ void __launch_bounds__(256, 1)
k_out(const float* __restrict__ lab_b1, const float* __restrict__ lab_b2,
      const float* __restrict__ spl_b1, const float* __restrict__ spl_w2,
      const float* __restrict__ spl_b2, float* __restrict__ out) {
    extern __shared__ char sm[];
    ull*   W2P  = (ull*)sm;
    float* HID2 = (float*)(sm + SM_HID);
    float* LB1  = (float*)(sm + SM_LB1);
    float* SB1  = (float*)(sm + SM_SB1);
    float* SW2  = (float*)(sm + SM_SW2);
    float* LB2  = (float*)(sm + SM_LB2);
    int tid = threadIdx.x;
    int j0 = blockIdx.x * 16, i0 = blockIdx.y * 4;

    {
        const float4* src = (const float4*)g_w2p;
        float4* dst = (float4*)W2P;
        for (int it = tid; it < 8192; it += 256) dst[it] = src[it];
    }
    LB1[tid] = lab_b1[tid];
    SB1[tid] = spl_b1[tid];
    SW2[tid] = spl_w2[tid];
    if (tid < 128) LB2[tid] = lab_b2[tid];
    __syncthreads();

    int wp = tid >> 5, lane = tid & 31;
    float sb2 = spl_b2[0];
    for (int px = 0; px < 8; ++px) {
        int p = wp * 8 + px;
        int i = i0 + (p >> 4), j = j0 + (p & 15);
        int ic = min(i, NP - 1), jc = min(j, NP - 1);
        const float* Uj = g_U[jc]; const float* Ui = g_U[ic];
        const float* Vj = g_V[jc]; const float* Vi = g_V[ic];
        float sacc = 0.f;
#pragma unroll
        for (int m = 0; m < 8; ++m) {
            int k = m * 32 + lane;
            HID2[p * HIDSTR + k] = fmaxf(Uj[k] - Ui[k] + LB1[k], 0.f);
            sacc += fmaxf(Vj[k] - Vi[k] + SB1[k], 0.f) * SW2[k];
        }
#pragma unroll
        for (int off = 16; off; off >>= 1)
            sacc += __shfl_xor_sync(0xffffffffu, sacc, off);
        if (lane == 0 && i < NP && j < NP)
            out[i * OSTR + j * 129 + 128] = sacc + sb2;
    }
    __syncthreads();

    int pg = tid >> 4, cg = tid & 15;
    ull acc[4][4];
#pragma unroll
    for (int a = 0; a < 4; ++a)
#pragma unroll
        for (int b = 0; b < 4; ++b) acc[a][b] = 0ULL;

    const float* hb = HID2 + pg * 4 * HIDSTR;
    const ull*  wb = W2P + cg;
#pragma unroll 2
    for (int k = 0; k < 256; ++k) {
        float h0 = hb[k], h1 = hb[HIDSTR + k], h2 = hb[2 * HIDSTR + k], h3 = hb[3 * HIDSTR + k];
        ull H0 = pack2(h0, h0), H1 = pack2(h1, h1), H2 = pack2(h2, h2), H3 = pack2(h3, h3);
        ull w0 = wb[k * 64], w1 = wb[k * 64 + 16], w2 = wb[k * 64 + 32], w3 = wb[k * 64 + 48];
        ffma2(acc[0][0], H0, w0); ffma2(acc[0][1], H0, w1); ffma2(acc[0][2], H0, w2); ffma2(acc[0][3], H0, w3);
        ffma2(acc[1][0], H1, w0); ffma2(acc[1][1], H1, w1); ffma2(acc[1][2], H1, w2); ffma2(acc[1][3], H1, w3);
        ffma2(acc[2][0], H2, w0); ffma2(acc[2][1], H2, w1); ffma2(acc[2][2], H2, w2); ffma2(acc[2][3], H2, w3);
        ffma2(acc[3][0], H3, w0); ffma2(acc[3][1], H3, w1); ffma2(acc[3][2], H3, w2); ffma2(acc[3][3], H3, w3);
    }
#pragma unroll
    for (int pp = 0; pp < 4; ++pp) {
        int p = pg * 4 + pp;
        int i = i0 + (p >> 4), j = j0 + (p & 15);
        if (i >= NP || j >= NP) continue;
        float* o = out + i * OSTR + j * 129;
#pragma unroll
        for (int q = 0; q < 4; ++q) {
            int cp = cg + 16 * q;
            float lo, hi; unpack2(acc[pp][q], lo, hi);
            o[2 * cp]     = lo + LB2[2 * cp];
            o[2 * cp + 1] = hi + LB2[2 * cp + 1];
        }
    }
}

extern "C" void kernel_launch(void* const* d_in, const int* in_sizes, int n_in,
                              void* d_out, int out_size) {
    const int*   tag_ids  = (const int*)d_in[0];
    const int*   word_ids = (const int*)d_in[1];
    const float* tag_emb  = (const float*)d_in[2];
    const float* word_emb = (const float*)d_in[3];
    const float* wxf = (const float*)d_in[4];
    const float* whf = (const float*)d_in[5];
    const float* bf  = (const float*)d_in[6];
    const float* wxb = (const float*)d_in[7];
    const float* whb = (const float*)d_in[8];
    const float* bb  = (const float*)d_in[9];
    const float* lab_w1 = (const float*)d_in[10];
    const float* lab_b1 = (const float*)d_in[11];
    const float* lab_w2 = (const float*)d_in[12];
    const float* lab_b2 = (const float*)d_in[13];
    const float* spl_w1 = (const float*)d_in[14];
    const float* spl_b1 = (const float*)d_in[15];
    const float* spl_w2 = (const float*)d_in[16];
    const float* spl_b2 = (const float*)d_in[17];
    float* out = (float*)d_out;

    static int smem_set = 0;
    if (!smem_set) {
        cudaFuncSetAttribute(k_out, cudaFuncAttributeMaxDynamicSharedMemorySize, SM_TOTAL);
        smem_set = 1;
    }

    k_embed<<<SEQ, EMB>>>(tag_ids, word_ids, tag_emb, word_emb);
    k_w2pack<<<64, 256>>>(lab_w2);
    k_xpre<<<dim3(49, 2), 1024>>>(wxf, bf, wxb, bb);
    k_lstm<<<16, 512>>>(whf, whb);
    k_uv<<<dim3(193, 2), 256>>>(lab_w1, spl_w1);
    k_out<<<dim3(25, 97), 256, SM_TOTAL>>>(lab_b1, lab_b2, spl_b1, spl_w2, spl_b2, out);
}

// round 16
// speedup vs baseline: 2.8489x; 1.0369x over previous
#include <cuda_runtime.h>
#include <cuda_bf16.h>
#include <cstdint>

#define SEQ 386
#define NP  385
#define HH  256
#define EMB 128
#define G4  1024
#define OSTR (385*129)

typedef unsigned long long ull;

__device__ float g_emb[SEQ][EMB];
__device__ float g_xpre[2][SEQ][G4];
__device__ float g_h[2][SEQ][HH];
__device__ float g_U[NP][HH];
__device__ float g_V[NP][HH];
__device__ ull   g_w2p[256 * 64];   // [k][cpair] packed label w2

__device__ __forceinline__ ull pack2(float lo, float hi) {
    ull r; asm("mov.b64 %0, {%1, %2};" : "=l"(r) : "f"(lo), "f"(hi)); return r;
}
__device__ __forceinline__ void unpack2(ull v, float& lo, float& hi) {
    asm("mov.b64 {%0, %1}, %2;" : "=f"(lo), "=f"(hi) : "l"(v));
}
__device__ __forceinline__ void ffma2(ull& d, ull a, ull b) {
    asm("fma.rn.f32x2 %0, %1, %2, %0;" : "+l"(d) : "l"(a), "l"(b));
}
__device__ __forceinline__ unsigned smem_u32(const void* p) {
    unsigned a;
    asm("{ .reg .u64 t; cvta.to.shared.u64 t, %1; cvt.u32.u64 %0, t; }" : "=r"(a) : "l"(p));
    return a;
}
__device__ __forceinline__ unsigned mapa_rank(unsigned addr, int rank) {
    unsigned ra;
    asm volatile("mapa.shared::cluster.u32 %0, %1, %2;" : "=r"(ra) : "r"(addr), "r"(rank));
    return ra;
}
__device__ __forceinline__ void mbar_init(unsigned addr, unsigned cnt) {
    asm volatile("mbarrier.init.shared.b64 [%0], %1;" :: "r"(addr), "r"(cnt) : "memory");
}
__device__ __forceinline__ void mbar_expect_tx(unsigned addr, unsigned bytes) {
    asm volatile("mbarrier.arrive.expect_tx.shared.b64 _, [%0], %1;"
                 :: "r"(addr), "r"(bytes) : "memory");
}
__device__ __forceinline__ void mbar_wait(unsigned addr, unsigned parity) {
    asm volatile(
        "{\n\t.reg .pred P;\n\t"
        "LW_%=:\n\t"
        "mbarrier.try_wait.parity.acquire.cluster.shared::cta.b64 P, [%0], %1, 0x989680;\n\t"
        "@P bra.uni LD_%=;\n\t"
        "bra.uni LW_%=;\n\t"
        "LD_%=:\n\t}"
        :: "r"(addr), "r"(parity) : "memory");
}
__device__ __forceinline__ void bulk_s2s(unsigned dst, unsigned src, unsigned bytes, unsigned rbar) {
    asm volatile(
        "cp.async.bulk.shared::cluster.shared::cta.mbarrier::complete_tx::bytes [%0], [%1], %2, [%3];"
        :: "r"(dst), "r"(src), "r"(bytes), "r"(rbar) : "memory");
}
__device__ __forceinline__ void fence_async_() {
    asm volatile("fence.proxy.async.shared::cta;" ::: "memory");
}
__device__ __forceinline__ void cluster_sync_() {
    asm volatile("barrier.cluster.arrive.aligned;" ::: "memory");
    asm volatile("barrier.cluster.wait.aligned;" ::: "memory");
}
__device__ __forceinline__ float sigx(float x)  { return __fdividef(1.f, 1.f + __expf(-x)); }
__device__ __forceinline__ float tanhx(float x) { return 2.f * __fdividef(1.f, 1.f + __expf(-2.f * x)) - 1.f; }

// ---------- K1: embeddings ----------
__global__ void k_embed(const int* __restrict__ tg, const int* __restrict__ wd,
                        const float* __restrict__ te, const float* __restrict__ we) {
    int t = blockIdx.x, d = threadIdx.x;
    g_emb[t][d] = te[tg[t] * EMB + d] + we[wd[t] * EMB + d];
}

// ---------- K1b: pack label w2 ----------
__global__ void k_w2pack(const float* __restrict__ lab_w2) {
    int idx = blockIdx.x * 256 + threadIdx.x;
    int cp = idx >> 8, k = idx & 255;
    g_w2p[k * 64 + cp] = pack2(lab_w2[(2 * cp) * 256 + k], lab_w2[(2 * cp + 1) * 256 + k]);
}

// ---------- K2: x preactivations ----------
__global__ void __launch_bounds__(1024, 1)
k_xpre(const float* __restrict__ wxf, const float* __restrict__ bfp,
       const float* __restrict__ wxb, const float* __restrict__ bbp) {
    __shared__ float se[8][128];
    __shared__ float wt[1024][9];
    int tid = threadIdx.x, t0 = blockIdx.x * 8, dir = blockIdx.y;
    {
        int tp = tid >> 7, d = tid & 127, t = t0 + tp;
        se[tp][d] = (t < SEQ) ? g_emb[t][d] : 0.f;
    }
    const float* Wx = dir ? wxb : wxf;
    const float* bp = dir ? bbp : bfp;
    float acc[8] = {0, 0, 0, 0, 0, 0, 0, 0};
    for (int d0 = 0; d0 < 128; d0 += 8) {
        __syncthreads();
#pragma unroll
        for (int it = 0; it < 8; ++it) {
            int idx = tid + it * 1024;
            int row = idx >> 3, dd = idx & 7;
            wt[row][dd] = Wx[row * 128 + d0 + dd];
        }
        __syncthreads();
#pragma unroll
        for (int dd = 0; dd < 8; ++dd) {
            float w = wt[tid][dd];
#pragma unroll
            for (int tp = 0; tp < 8; ++tp) acc[tp] += w * se[tp][d0 + dd];
        }
    }
    float bias = bp[tid];
#pragma unroll
    for (int tp = 0; tp < 8; ++tp) {
        int t = t0 + tp;
        if (t < SEQ) g_xpre[dir][t][tid] = acc[tp] + bias;
    }
}

// ---------- K3: BiLSTM — warp-quarter partials, single-warp h production,
//             quarter-mbarriers + 128B bulk scatter. 8-CTA cluster per dir. ----------
__global__ void __cluster_dims__(8, 1, 1) __launch_bounds__(512, 1)
k_lstm(const float* __restrict__ whf, const float* __restrict__ whb) {
    __shared__ __align__(16) float hbuf[2][HH];
    __shared__ __align__(16) float part[2][4][32][4];   // [buf][gate][unit][quarter]
    __shared__ __align__(16) float stag[2][32];
    __shared__ __align__(8)  ull  mbar[2][4];           // [buf][quarter]
    int tid = threadIdx.x;
    int dir = blockIdx.x >> 3, rank = blockIdx.x & 7;
    int w = tid >> 5, lane = tid & 31;
    int gt = w >> 2, p = w & 3;
    int row = gt * 256 + rank * 32 + lane;
    const float* Wh = dir ? whb : whf;

    // 32 weight pairs: k in [64p, 64p+64) for this row (contiguous, no rotation:
    // h loads below are warp-uniform broadcasts, inherently conflict-free)
    ull wreg[32];
#pragma unroll
    for (int m = 0; m < 32; ++m) {
        const float* wp = Wh + row * 256 + p * 64 + 2 * m;
        wreg[m] = pack2(wp[0], wp[1]);
    }
    ((float*)hbuf)[tid] = 0.f;   // zero both 256-float buffers
    if (tid < 8) {
        unsigned mb = smem_u32(&mbar[tid >> 2][tid & 3]);
        mbar_init(mb, 1);
        mbar_expect_tx(mb, 256);  // phase 0: 2 source CTAs x 128B
    }
    __syncthreads();
    cluster_sync_();   // mbarriers armed cluster-wide before any copy

    unsigned mymb[2] = { smem_u32(&mbar[0][p]), smem_u32(&mbar[1][p]) };
    unsigned ph[2] = { 0, 0 };
    bool isw0 = (w == 0);
    bool xowner = (p == 0);
    float c_state = 0.f;
    int t = dir ? (SEQ - 1) : 0;
    float xcur = xowner ? g_xpre[dir][t][row] : 0.f;

    for (int s = 0; s < SEQ; ++s) {
        int cur = s & 1, nxt = cur ^ 1;
        int tn = dir ? (SEQ - 2 - s) : (s + 1);
        float xnext = (xowner && s < SEQ - 1) ? g_xpre[dir][tn][row] : 0.f;

        if (s) {   // wait this quarter's 2 incoming 128B copies
            mbar_wait(mymb[cur], ph[cur]); ph[cur] ^= 1;
            if (gt == 0 && lane == 0) mbar_expect_tx(mymb[cur], 256);  // re-arm for s+2
        }

        // partial dot over k in [64p, 64p+64): 16 broadcast LDS.128 + 32 FFMA2
        ull a0 = 0ULL, a1 = 0ULL;
        const float* hq = &hbuf[cur][p * 64];
#pragma unroll
        for (int m = 0; m < 8; ++m) {
            ulonglong2 h0 = *(const ulonglong2*)(hq + 8 * m);
            ulonglong2 h1 = *(const ulonglong2*)(hq + 8 * m + 4);
            ffma2(a0, wreg[4 * m],     h0.x);
            ffma2(a1, wreg[4 * m + 1], h0.y);
            ffma2(a0, wreg[4 * m + 2], h1.x);
            ffma2(a1, wreg[4 * m + 3], h1.y);
        }
        float x0, x1, y0, y1; unpack2(a0, x0, x1); unpack2(a1, y0, y1);
        part[cur][gt][lane][p] = (x0 + y0) + (x1 + y1) + xcur;
        __syncthreads();   // all partials visible to warp 0

        if (isw0) {
            float4 qi = *(const float4*)&part[cur][0][lane][0];
            float4 qf = *(const float4*)&part[cur][1][lane][0];
            float4 qg = *(const float4*)&part[cur][2][lane][0];
            float4 qo = *(const float4*)&part[cur][3][lane][0];
            float pi = (qi.x + qi.y) + (qi.z + qi.w);
            float pf = (qf.x + qf.y) + (qf.z + qf.w);
            float pg = (qg.x + qg.y) + (qg.z + qg.w);
            float po = (qo.x + qo.y) + (qo.z + qo.w);
            c_state = sigx(pf) * c_state + sigx(pi) * tanhx(pg);
            float hv = sigx(po) * tanhx(c_state);
            if (s < SEQ - 1) {
                // stag[cur] was last read by the bulk group of step s-2:
                // allow <=1 outstanding group before overwriting
                asm volatile("cp.async.bulk.wait_group.read 1;" ::: "memory");
                __syncwarp();
                stag[cur][lane] = hv;
                __syncwarp();
                if (lane < 8) {
                    fence_async_();
                    unsigned d  = mapa_rank(smem_u32(&hbuf[nxt][rank * 32]), lane);
                    unsigned mr = mapa_rank(smem_u32(&mbar[nxt][rank >> 1]), lane);
                    bulk_s2s(d, smem_u32(&stag[cur][0]), 128, mr);
                    asm volatile("cp.async.bulk.commit_group;" ::: "memory");
                }
            }
            g_h[dir][t][rank * 32 + lane] = hv;
        }
        t = tn;
        xcur = xnext;
    }
    cluster_sync_();
}

// ---------- K4: U/V span transforms ----------
__global__ void __launch_bounds__(256, 1)
k_uv(const float* __restrict__ lab_w1, const float* __restrict__ spl_w1) {
    __shared__ float sh2[512][2];
    int tid = threadIdx.x, k0 = blockIdx.x * 2, which = blockIdx.y;
    for (int idx = tid; idx < 1024; idx += 256) {
        int d = idx >> 1, kk = idx & 1, k = k0 + kk;
        float v = 0.f;
        if (k < NP) v = (d < 256) ? g_h[0][k][d] : -g_h[1][k + 1][d - 256];
        sh2[d][kk] = v;
    }
    __syncthreads();
    const float* w1 = which ? spl_w1 : lab_w1;
    int w = tid >> 5, lane = tid & 31;
    float (*dst)[HH] = which ? g_V : g_U;
#pragma unroll 2
    for (int cx = 0; cx < 32; ++cx) {
        int c = w * 32 + cx;
        const float* wr = w1 + c * 512;
        ull acc = 0ULL;
#pragma unroll
        for (int m = 0; m < 16; ++m) {
            int d = m * 32 + lane;
            float wv = wr[d];
            ffma2(acc, pack2(wv, wv), *(const ull*)&sh2[d][0]);
        }
        float a, b; unpack2(acc, a, b);
#pragma unroll
        for (int off = 16; off; off >>= 1) {
            a += __shfl_xor_sync(0xffffffffu, a, off);
            b += __shfl_xor_sync(0xffffffffu, b, off);
        }
        if (lane == 0) {
            if (k0     < NP) dst[k0    ][c] = a;
            if (k0 + 1 < NP) dst[k0 + 1][c] = b;
        }
    }
}

// ---------- K5: pairwise outputs ----------
#define HIDSTR 260
#define SM_HID   131072
#define SM_LB1   (SM_HID + 64 * HIDSTR * 4)
#define SM_SB1   (SM_LB1 + 1024)
#define SM_SW2   (SM_SB1 + 1024)
#define SM_LB2   (SM_SW2 + 1024)
#define SM_TOTAL (SM_LB2 + 512)

__global__ void __launch_bounds__(256, 1)
k_out(const float* __restrict__ lab_b1, const float* __restrict__ lab_b2,
      const float* __restrict__ spl_b1, const float* __restrict__ spl_w2,
      const float* __restrict__ spl_b2, float* __restrict__ out) {
    extern __shared__ char sm[];
    ull*   W2P  = (ull*)sm;
    float* HID2 = (float*)(sm + SM_HID);
    float* LB1  = (float*)(sm + SM_LB1);
    float* SB1  = (float*)(sm + SM_SB1);
    float* SW2  = (float*)(sm + SM_SW2);
    float* LB2  = (float*)(sm + SM_LB2);
    int tid = threadIdx.x;
    int j0 = blockIdx.x * 16, i0 = blockIdx.y * 4;

    {
        const float4* src = (const float4*)g_w2p;
        float4* dst = (float4*)W2P;
        for (int it = tid; it < 8192; it += 256) dst[it] = src[it];
    }
    LB1[tid] = lab_b1[tid];
    SB1[tid] = spl_b1[tid];
    SW2[tid] = spl_w2[tid];
    if (tid < 128) LB2[tid] = lab_b2[tid];
    __syncthreads();

    int wp = tid >> 5, lane = tid & 31;
    float sb2 = spl_b2[0];
    for (int px = 0; px < 8; ++px) {
        int p = wp * 8 + px;
        int i = i0 + (p >> 4), j = j0 + (p & 15);
        int ic = min(i, NP - 1), jc = min(j, NP - 1);
        const float* Uj = g_U[jc]; const float* Ui = g_U[ic];
        const float* Vj = g_V[jc]; const float* Vi = g_V[ic];
        float sacc = 0.f;
#pragma unroll
        for (int m = 0; m < 8; ++m) {
            int k = m * 32 + lane;
            HID2[p * HIDSTR + k] = fmaxf(Uj[k] - Ui[k] + LB1[k], 0.f);
            sacc += fmaxf(Vj[k] - Vi[k] + SB1[k], 0.f) * SW2[k];
        }
#pragma unroll
        for (int off = 16; off; off >>= 1)
            sacc += __shfl_xor_sync(0xffffffffu, sacc, off);
        if (lane == 0 && i < NP && j < NP)
            out[i * OSTR + j * 129 + 128] = sacc + sb2;
    }
    __syncthreads();

    int pg = tid >> 4, cg = tid & 15;
    ull acc[4][4];
#pragma unroll
    for (int a = 0; a < 4; ++a)
#pragma unroll
        for (int b = 0; b < 4; ++b) acc[a][b] = 0ULL;

    const float* hb = HID2 + pg * 4 * HIDSTR;
    const ull*  wb = W2P + cg;
#pragma unroll 2
    for (int k = 0; k < 256; ++k) {
        float h0 = hb[k], h1 = hb[HIDSTR + k], h2 = hb[2 * HIDSTR + k], h3 = hb[3 * HIDSTR + k];
        ull H0 = pack2(h0, h0), H1 = pack2(h1, h1), H2 = pack2(h2, h2), H3 = pack2(h3, h3);
        ull w0 = wb[k * 64], w1 = wb[k * 64 + 16], w2 = wb[k * 64 + 32], w3 = wb[k * 64 + 48];
        ffma2(acc[0][0], H0, w0); ffma2(acc[0][1], H0, w1); ffma2(acc[0][2], H0, w2); ffma2(acc[0][3], H0, w3);
        ffma2(acc[1][0], H1, w0); ffma2(acc[1][1], H1, w1); ffma2(acc[1][2], H1, w2); ffma2(acc[1][3], H1, w3);
        ffma2(acc[2][0], H2, w0); ffma2(acc[2][1], H2, w1); ffma2(acc[2][2], H2, w2); ffma2(acc[2][3], H2, w3);
        ffma2(acc[3][0], H3, w0); ffma2(acc[3][1], H3, w1); ffma2(acc[3][2], H3, w2); ffma2(acc[3][3], H3, w3);
    }
#pragma unroll
    for (int pp = 0; pp < 4; ++pp) {
        int p = pg * 4 + pp;
        int i = i0 + (p >> 4), j = j0 + (p & 15);
        if (i >= NP || j >= NP) continue;
        float* o = out + i * OSTR + j * 129;
#pragma unroll
        for (int q = 0; q < 4; ++q) {
            int cp = cg + 16 * q;
            float lo, hi; unpack2(acc[pp][q], lo, hi);
            o[2 * cp]     = lo + LB2[2 * cp];
            o[2 * cp + 1] = hi + LB2[2 * cp + 1];
        }
    }
}

extern "C" void kernel_launch(void* const* d_in, const int* in_sizes, int n_in,
                              void* d_out, int out_size) {
    const int*   tag_ids  = (const int*)d_in[0];
    const int*   word_ids = (const int*)d_in[1];
    const float* tag_emb  = (const float*)d_in[2];
    const float* word_emb = (const float*)d_in[3];
    const float* wxf = (const float*)d_in[4];
    const float* whf = (const float*)d_in[5];
    const float* bf  = (const float*)d_in[6];
    const float* wxb = (const float*)d_in[7];
    const float* whb = (const float*)d_in[8];
    const float* bb  = (const float*)d_in[9];
    const float* lab_w1 = (const float*)d_in[10];
    const float* lab_b1 = (const float*)d_in[11];
    const float* lab_w2 = (const float*)d_in[12];
    const float* lab_b2 = (const float*)d_in[13];
    const float* spl_w1 = (const float*)d_in[14];
    const float* spl_b1 = (const float*)d_in[15];
    const float* spl_w2 = (const float*)d_in[16];
    const float* spl_b2 = (const float*)d_in[17];
    float* out = (float*)d_out;

    static int smem_set = 0;
    if (!smem_set) {
        cudaFuncSetAttribute(k_out, cudaFuncAttributeMaxDynamicSharedMemorySize, SM_TOTAL);
        smem_set = 1;
    }

    k_embed<<<SEQ, EMB>>>(tag_ids, word_ids, tag_emb, word_emb);
    k_w2pack<<<64, 256>>>(lab_w2);
    k_xpre<<<dim3(49, 2), 1024>>>(wxf, bf, wxb, bb);
    k_lstm<<<16, 512>>>(whf, whb);
    k_uv<<<dim3(193, 2), 256>>>(lab_w1, spl_w1);
    k_out<<<dim3(25, 97), 256, SM_TOTAL>>>(lab_b1, lab_b2, spl_b1, spl_w2, spl_b2, out);
}

// round 17
// speedup vs baseline: 3.0245x; 1.0617x over previous
#include <cuda_runtime.h>
#include <cuda_bf16.h>
#include <cstdint>

#define SEQ 386
#define NP  385
#define HH  256
#define EMB 128
#define G4  1024
#define OSTR (385*129)

typedef unsigned long long ull;

__device__ float g_emb[SEQ][EMB];
__device__ float g_xpre[2][SEQ][G4];
__device__ float g_h[2][SEQ][HH];
__device__ float g_U[NP][HH];
__device__ float g_V[NP][HH];
__device__ ull   g_w2p[256 * 64];   // [k][cpair] packed label w2

__device__ __forceinline__ ull pack2(float lo, float hi) {
    ull r; asm("mov.b64 %0, {%1, %2};" : "=l"(r) : "f"(lo), "f"(hi)); return r;
}
__device__ __forceinline__ void unpack2(ull v, float& lo, float& hi) {
    asm("mov.b64 {%0, %1}, %2;" : "=f"(lo), "=f"(hi) : "l"(v));
}
__device__ __forceinline__ void ffma2(ull& d, ull a, ull b) {
    asm("fma.rn.f32x2 %0, %1, %2, %0;" : "+l"(d) : "l"(a), "l"(b));
}
__device__ __forceinline__ unsigned smem_u32(const void* p) {
    unsigned a;
    asm("{ .reg .u64 t; cvta.to.shared.u64 t, %1; cvt.u32.u64 %0, t; }" : "=r"(a) : "l"(p));
    return a;
}
__device__ __forceinline__ unsigned mapa_rank(unsigned addr, int rank) {
    unsigned ra;
    asm volatile("mapa.shared::cluster.u32 %0, %1, %2;" : "=r"(ra) : "r"(addr), "r"(rank));
    return ra;
}
__device__ __forceinline__ void mbar_init(unsigned addr, unsigned cnt) {
    asm volatile("mbarrier.init.shared.b64 [%0], %1;" :: "r"(addr), "r"(cnt) : "memory");
}
__device__ __forceinline__ void mbar_expect_tx(unsigned addr, unsigned bytes) {
    asm volatile("mbarrier.arrive.expect_tx.shared.b64 _, [%0], %1;"
                 :: "r"(addr), "r"(bytes) : "memory");
}
// CTA-scope acquire: canonical consumer wait for async-proxy (bulk/TMA) writes
// into local SMEM signaled via complete_tx. Cluster-scope acquire (previous
// rounds) drags a >=cluster fence (CCTL.IVALL class) onto every step.
__device__ __forceinline__ void mbar_wait(unsigned addr, unsigned parity) {
    asm volatile(
        "{\n\t.reg .pred P;\n\t"
        "LW_%=:\n\t"
        "mbarrier.try_wait.parity.acquire.cta.shared::cta.b64 P, [%0], %1, 0x989680;\n\t"
        "@P bra.uni LD_%=;\n\t"
        "bra.uni LW_%=;\n\t"
        "LD_%=:\n\t}"
        :: "r"(addr), "r"(parity) : "memory");
}
__device__ __forceinline__ void bulk_s2s(unsigned dst, unsigned src, unsigned bytes, unsigned rbar) {
    asm volatile(
        "cp.async.bulk.shared::cluster.shared::cta.mbarrier::complete_tx::bytes [%0], [%1], %2, [%3];"
        :: "r"(dst), "r"(src), "r"(bytes), "r"(rbar) : "memory");
}
__device__ __forceinline__ void fence_async_() {
    asm volatile("fence.proxy.async.shared::cta;" ::: "memory");
}
__device__ __forceinline__ void cluster_sync_() {
    asm volatile("barrier.cluster.arrive.aligned;" ::: "memory");
    asm volatile("barrier.cluster.wait.aligned;" ::: "memory");
}
__device__ __forceinline__ float sigx(float x)  { return __fdividef(1.f, 1.f + __expf(-x)); }
__device__ __forceinline__ float tanhx(float x) { return 2.f * __fdividef(1.f, 1.f + __expf(-2.f * x)) - 1.f; }

// ---------- K1: embeddings ----------
__global__ void k_embed(const int* __restrict__ tg, const int* __restrict__ wd,
                        const float* __restrict__ te, const float* __restrict__ we) {
    int t = blockIdx.x, d = threadIdx.x;
    g_emb[t][d] = te[tg[t] * EMB + d] + we[wd[t] * EMB + d];
}

// ---------- K1b: pack label w2 ----------
__global__ void k_w2pack(const float* __restrict__ lab_w2) {
    int idx = blockIdx.x * 256 + threadIdx.x;
    int cp = idx >> 8, k = idx & 255;
    g_w2p[k * 64 + cp] = pack2(lab_w2[(2 * cp) * 256 + k], lab_w2[(2 * cp + 1) * 256 + k]);
}

// ---------- K2: x preactivations ----------
__global__ void __launch_bounds__(1024, 1)
k_xpre(const float* __restrict__ wxf, const float* __restrict__ bfp,
       const float* __restrict__ wxb, const float* __restrict__ bbp) {
    __shared__ float se[8][128];
    __shared__ float wt[1024][9];
    int tid = threadIdx.x, t0 = blockIdx.x * 8, dir = blockIdx.y;
    {
        int tp = tid >> 7, d = tid & 127, t = t0 + tp;
        se[tp][d] = (t < SEQ) ? g_emb[t][d] : 0.f;
    }
    const float* Wx = dir ? wxb : wxf;
    const float* bp = dir ? bbp : bfp;
    float acc[8] = {0, 0, 0, 0, 0, 0, 0, 0};
    for (int d0 = 0; d0 < 128; d0 += 8) {
        __syncthreads();
#pragma unroll
        for (int it = 0; it < 8; ++it) {
            int idx = tid + it * 1024;
            int row = idx >> 3, dd = idx & 7;
            wt[row][dd] = Wx[row * 128 + d0 + dd];
        }
        __syncthreads();
#pragma unroll
        for (int dd = 0; dd < 8; ++dd) {
            float w = wt[tid][dd];
#pragma unroll
            for (int tp = 0; tp < 8; ++tp) acc[tp] += w * se[tp][d0 + dd];
        }
    }
    float bias = bp[tid];
#pragma unroll
    for (int tp = 0; tp < 8; ++tp) {
        int t = t0 + tp;
        if (t < SEQ) g_xpre[dir][t][tid] = acc[tp] + bias;
    }
}

// ---------- K3: BiLSTM — warp-quarter partials, single-warp h production,
//             quarter-mbarriers + 128B bulk scatter. 8-CTA cluster per dir. ----------
__global__ void __cluster_dims__(8, 1, 1) __launch_bounds__(512, 1)
k_lstm(const float* __restrict__ whf, const float* __restrict__ whb) {
    __shared__ __align__(16) float hbuf[2][HH];
    __shared__ __align__(16) float part[2][4][32][4];   // [buf][gate][unit][quarter]
    __shared__ __align__(16) float stag[2][32];
    __shared__ __align__(8)  ull  mbar[2][4];           // [buf][quarter]
    int tid = threadIdx.x;
    int dir = blockIdx.x >> 3, rank = blockIdx.x & 7;
    int w = tid >> 5, lane = tid & 31;
    int gt = w >> 2, p = w & 3;
    int row = gt * 256 + rank * 32 + lane;
    const float* Wh = dir ? whb : whf;

    // 32 weight pairs: k in [64p, 64p+64) for this row (contiguous; h loads
    // below are warp-uniform broadcasts, inherently conflict-free)
    ull wreg[32];
#pragma unroll
    for (int m = 0; m < 32; ++m) {
        const float* wp = Wh + row * 256 + p * 64 + 2 * m;
        wreg[m] = pack2(wp[0], wp[1]);
    }
    ((float*)hbuf)[tid] = 0.f;   // zero both 256-float buffers
    if (tid < 8) {
        unsigned mb = smem_u32(&mbar[tid >> 2][tid & 3]);
        mbar_init(mb, 1);
        mbar_expect_tx(mb, 256);  // phase 0: 2 source CTAs x 128B
    }
    __syncthreads();
    cluster_sync_();   // mbarriers armed cluster-wide before any copy

    unsigned mymb[2] = { smem_u32(&mbar[0][p]), smem_u32(&mbar[1][p]) };
    unsigned ph[2] = { 0, 0 };
    bool isw0 = (w == 0);
    bool xowner = (p == 0);
    float c_state = 0.f;
    int t = dir ? (SEQ - 1) : 0;
    float xcur = xowner ? g_xpre[dir][t][row] : 0.f;

    for (int s = 0; s < SEQ; ++s) {
        int cur = s & 1, nxt = cur ^ 1;
        int tn = dir ? (SEQ - 2 - s) : (s + 1);
        float xnext = (xowner && s < SEQ - 1) ? g_xpre[dir][tn][row] : 0.f;

        if (s) {   // wait this quarter's 2 incoming 128B copies
            mbar_wait(mymb[cur], ph[cur]); ph[cur] ^= 1;
            if (gt == 0 && lane == 0) mbar_expect_tx(mymb[cur], 256);  // re-arm for s+2
        }

        // partial dot over k in [64p, 64p+64): 16 broadcast LDS.128 + 32 FFMA2
        ull a0 = 0ULL, a1 = 0ULL;
        const float* hq = &hbuf[cur][p * 64];
#pragma unroll
        for (int m = 0; m < 8; ++m) {
            ulonglong2 h0 = *(const ulonglong2*)(hq + 8 * m);
            ulonglong2 h1 = *(const ulonglong2*)(hq + 8 * m + 4);
            ffma2(a0, wreg[4 * m],     h0.x);
            ffma2(a1, wreg[4 * m + 1], h0.y);
            ffma2(a0, wreg[4 * m + 2], h1.x);
            ffma2(a1, wreg[4 * m + 3], h1.y);
        }
        float x0, x1, y0, y1; unpack2(a0, x0, x1); unpack2(a1, y0, y1);
        part[cur][gt][lane][p] = (x0 + y0) + (x1 + y1) + xcur;
        __syncthreads();   // all partials visible to warp 0

        if (isw0) {
            float4 qi = *(const float4*)&part[cur][0][lane][0];
            float4 qf = *(const float4*)&part[cur][1][lane][0];
            float4 qg = *(const float4*)&part[cur][2][lane][0];
            float4 qo = *(const float4*)&part[cur][3][lane][0];
            float pi = (qi.x + qi.y) + (qi.z + qi.w);
            float pf = (qf.x + qf.y) + (qf.z + qf.w);
            float pg = (qg.x + qg.y) + (qg.z + qg.w);
            float po = (qo.x + qo.y) + (qo.z + qo.w);
            c_state = sigx(pf) * c_state + sigx(pi) * tanhx(pg);
            float hv = sigx(po) * tanhx(c_state);
            if (s < SEQ - 1) {
                // stag[cur] was last read by the bulk group of step s-2:
                // allow <=1 outstanding group before overwriting
                asm volatile("cp.async.bulk.wait_group.read 1;" ::: "memory");
                __syncwarp();
                stag[cur][lane] = hv;
                __syncwarp();
                if (lane < 8) {
                    fence_async_();
                    unsigned d  = mapa_rank(smem_u32(&hbuf[nxt][rank * 32]), lane);
                    unsigned mr = mapa_rank(smem_u32(&mbar[nxt][rank >> 1]), lane);
                    bulk_s2s(d, smem_u32(&stag[cur][0]), 128, mr);
                    asm volatile("cp.async.bulk.commit_group;" ::: "memory");
                }
            }
            g_h[dir][t][rank * 32 + lane] = hv;
        }
        t = tn;
        xcur = xnext;
    }
    cluster_sync_();
}

// ---------- K4: U/V span transforms ----------
__global__ void __launch_bounds__(256, 1)
k_uv(const float* __restrict__ lab_w1, const float* __restrict__ spl_w1) {
    __shared__ float sh2[512][2];
    int tid = threadIdx.x, k0 = blockIdx.x * 2, which = blockIdx.y;
    for (int idx = tid; idx < 1024; idx += 256) {
        int d = idx >> 1, kk = idx & 1, k = k0 + kk;
        float v = 0.f;
        if (k < NP) v = (d < 256) ? g_h[0][k][d] : -g_h[1][k + 1][d - 256];
        sh2[d][kk] = v;
    }
    __syncthreads();
    const float* w1 = which ? spl_w1 : lab_w1;
    int w = tid >> 5, lane = tid & 31;
    float (*dst)[HH] = which ? g_V : g_U;
#pragma unroll 2
    for (int cx = 0; cx < 32; ++cx) {
        int c = w * 32 + cx;
        const float* wr = w1 + c * 512;
        ull acc = 0ULL;
#pragma unroll
        for (int m = 0; m < 16; ++m) {
            int d = m * 32 + lane;
            float wv = wr[d];
            ffma2(acc, pack2(wv, wv), *(const ull*)&sh2[d][0]);
        }
        float a, b; unpack2(acc, a, b);
#pragma unroll
        for (int off = 16; off; off >>= 1) {
            a += __shfl_xor_sync(0xffffffffu, a, off);
            b += __shfl_xor_sync(0xffffffffu, b, off);
        }
        if (lane == 0) {
            if (k0     < NP) dst[k0    ][c] = a;
            if (k0 + 1 < NP) dst[k0 + 1][c] = b;
        }
    }
}

// ---------- K5: pairwise outputs ----------
#define HIDSTR 260
#define SM_HID   131072
#define SM_LB1   (SM_HID + 64 * HIDSTR * 4)
#define SM_SB1   (SM_LB1 + 1024)
#define SM_SW2   (SM_SB1 + 1024)
#define SM_LB2   (SM_SW2 + 1024)
#define SM_TOTAL (SM_LB2 + 512)

__global__ void __launch_bounds__(256, 1)
k_out(const float* __restrict__ lab_b1, const float* __restrict__ lab_b2,
      const float* __restrict__ spl_b1, const float* __restrict__ spl_w2,
      const float* __restrict__ spl_b2, float* __restrict__ out) {
    extern __shared__ char sm[];
    ull*   W2P  = (ull*)sm;
    float* HID2 = (float*)(sm + SM_HID);
    float* LB1  = (float*)(sm + SM_LB1);
    float* SB1  = (float*)(sm + SM_SB1);
    float* SW2  = (float*)(sm + SM_SW2);
    float* LB2  = (float*)(sm + SM_LB2);
    int tid = threadIdx.x;
    int j0 = blockIdx.x * 16, i0 = blockIdx.y * 4;

    {
        const float4* src = (const float4*)g_w2p;
        float4* dst = (float4*)W2P;
        for (int it = tid; it < 8192; it += 256) dst[it] = src[it];
    }
    LB1[tid] = lab_b1[tid];
    SB1[tid] = spl_b1[tid];
    SW2[tid] = spl_w2[tid];
    if (tid < 128) LB2[tid] = lab_b2[tid];
    __syncthreads();

    int wp = tid >> 5, lane = tid & 31;
    float sb2 = spl_b2[0];
    for (int px = 0; px < 8; ++px) {
        int p = wp * 8 + px;
        int i = i0 + (p >> 4), j = j0 + (p & 15);
        int ic = min(i, NP - 1), jc = min(j, NP - 1);
        const float* Uj = g_U[jc]; const float* Ui = g_U[ic];
        const float* Vj = g_V[jc]; const float* Vi = g_V[ic];
        float sacc = 0.f;
#pragma unroll
        for (int m = 0; m < 8; ++m) {
            int k = m * 32 + lane;
            HID2[p * HIDSTR + k] = fmaxf(Uj[k] - Ui[k] + LB1[k], 0.f);
            sacc += fmaxf(Vj[k] - Vi[k] + SB1[k], 0.f) * SW2[k];
        }
#pragma unroll
        for (int off = 16; off; off >>= 1)
            sacc += __shfl_xor_sync(0xffffffffu, sacc, off);
        if (lane == 0 && i < NP && j < NP)
            out[i * OSTR + j * 129 + 128] = sacc + sb2;
    }
    __syncthreads();

    int pg = tid >> 4, cg = tid & 15;
    ull acc[4][4];
#pragma unroll
    for (int a = 0; a < 4; ++a)
#pragma unroll
        for (int b = 0; b < 4; ++b) acc[a][b] = 0ULL;

    const float* hb = HID2 + pg * 4 * HIDSTR;
    const ull*  wb = W2P + cg;
#pragma unroll 2
    for (int k = 0; k < 256; ++k) {
        float h0 = hb[k], h1 = hb[HIDSTR + k], h2 = hb[2 * HIDSTR + k], h3 = hb[3 * HIDSTR + k];
        ull H0 = pack2(h0, h0), H1 = pack2(h1, h1), H2 = pack2(h2, h2), H3 = pack2(h3, h3);
        ull w0 = wb[k * 64], w1 = wb[k * 64 + 16], w2 = wb[k * 64 + 32], w3 = wb[k * 64 + 48];
        ffma2(acc[0][0], H0, w0); ffma2(acc[0][1], H0, w1); ffma2(acc[0][2], H0, w2); ffma2(acc[0][3], H0, w3);
        ffma2(acc[1][0], H1, w0); ffma2(acc[1][1], H1, w1); ffma2(acc[1][2], H1, w2); ffma2(acc[1][3], H1, w3);
        ffma2(acc[2][0], H2, w0); ffma2(acc[2][1], H2, w1); ffma2(acc[2][2], H2, w2); ffma2(acc[2][3], H2, w3);
        ffma2(acc[3][0], H3, w0); ffma2(acc[3][1], H3, w1); ffma2(acc[3][2], H3, w2); ffma2(acc[3][3], H3, w3);
    }
#pragma unroll
    for (int pp = 0; pp < 4; ++pp) {
        int p = pg * 4 + pp;
        int i = i0 + (p >> 4), j = j0 + (p & 15);
        if (i >= NP || j >= NP) continue;
        float* o = out + i * OSTR + j * 129;
#pragma unroll
        for (int q = 0; q < 4; ++q) {
            int cp = cg + 16 * q;
            float lo, hi; unpack2(acc[pp][q], lo, hi);
            o[2 * cp]     = lo + LB2[2 * cp];
            o[2 * cp + 1] = hi + LB2[2 * cp + 1];
        }
    }
}

extern "C" void kernel_launch(void* const* d_in, const int* in_sizes, int n_in,
                              void* d_out, int out_size) {
    const int*   tag_ids  = (const int*)d_in[0];
    const int*   word_ids = (const int*)d_in[1];
    const float* tag_emb  = (const float*)d_in[2];
    const float* word_emb = (const float*)d_in[3];
    const float* wxf = (const float*)d_in[4];
    const float* whf = (const float*)d_in[5];
    const float* bf  = (const float*)d_in[6];
    const float* wxb = (const float*)d_in[7];
    const float* whb = (const float*)d_in[8];
    const float* bb  = (const float*)d_in[9];
    const float* lab_w1 = (const float*)d_in[10];
    const float* lab_b1 = (const float*)d_in[11];
    const float* lab_w2 = (const float*)d_in[12];
    const float* lab_b2 = (const float*)d_in[13];
    const float* spl_w1 = (const float*)d_in[14];
    const float* spl_b1 = (const float*)d_in[15];
    const float* spl_w2 = (const float*)d_in[16];
    const float* spl_b2 = (const float*)d_in[17];
    float* out = (float*)d_out;

    static int smem_set = 0;
    if (!smem_set) {
        cudaFuncSetAttribute(k_out, cudaFuncAttributeMaxDynamicSharedMemorySize, SM_TOTAL);
        smem_set = 1;
    }

    k_embed<<<SEQ, EMB>>>(tag_ids, word_ids, tag_emb, word_emb);
    k_w2pack<<<64, 256>>>(lab_w2);
    k_xpre<<<dim3(49, 2), 1024>>>(wxf, bf, wxb, bb);
    k_lstm<<<16, 512>>>(whf, whb);
    k_uv<<<dim3(193, 2), 256>>>(lab_w1, spl_w1);
    k_out<<<dim3(25, 97), 256, SM_TOTAL>>>(lab_b1, lab_b2, spl_b1, spl_w2, spl_b2, out);
}